// round 3
// baseline (speedup 1.0000x reference)
#include <cuda_runtime.h>
#include <cuda_bf16.h>
#include <cstddef>
#include <cstdint>

#define T_STEPS 200
#define BATCH   4096
#define OBS     64
#define HID     128
#define NENC    50

#define RECON_ELEMS ((size_t)T_STEPS * BATCH * OBS)
#define ZM_ELEMS    ((size_t)BATCH * 3)

// Scratch (static device arrays; no runtime allocation)
__device__ float g_gi[(size_t)NENC * BATCH * 3 * HID];
__device__ float g_hlast[(size_t)BATCH * HID];
__device__ float g_z0[(size_t)BATCH * 3];

__device__ __forceinline__ float fsigmoid(float x) {
    return __fdividef(1.0f, 1.0f + __expf(-x));
}
__device__ __forceinline__ float ftanh(float x) {
    return 1.0f - __fdividef(2.0f, __expf(2.0f * x) + 1.0f);
}

// ===========================================================================
// Kernel 1: GI = obs[:50] @ Wih^T + bih  (NT SGEMM M=204800, N=384, K=64)
// ===========================================================================
__global__ void gi_gemm_kernel(const float* __restrict__ A,
                               const float* __restrict__ B,
                               const float* __restrict__ bias)
{
    __shared__ float As[16][128];
    __shared__ float Bs[16][128];
    const int tid = threadIdx.x;
    const int bm = blockIdx.x * 128;
    const int bn = blockIdx.y * 128;
    const int tx = tid & 15;
    const int ty = tid >> 4;

    float acc[8][8];
#pragma unroll
    for (int i = 0; i < 8; ++i)
#pragma unroll
        for (int j = 0; j < 8; ++j) acc[i][j] = 0.0f;

    for (int kk = 0; kk < 64; kk += 16) {
#pragma unroll
        for (int l = 0; l < 2; ++l) {
            int fi = tid + 256 * l;
            int row = fi >> 2;
            int kq = fi & 3;
            float4 va = *(const float4*)(A + (size_t)(bm + row) * 64 + kk + kq * 4);
            As[kq * 4 + 0][row] = va.x; As[kq * 4 + 1][row] = va.y;
            As[kq * 4 + 2][row] = va.z; As[kq * 4 + 3][row] = va.w;
            float4 vb = *(const float4*)(B + (size_t)(bn + row) * 64 + kk + kq * 4);
            Bs[kq * 4 + 0][row] = vb.x; Bs[kq * 4 + 1][row] = vb.y;
            Bs[kq * 4 + 2][row] = vb.z; Bs[kq * 4 + 3][row] = vb.w;
        }
        __syncthreads();
#pragma unroll
        for (int k = 0; k < 16; ++k) {
            float4 a0 = *(const float4*)&As[k][ty * 8];
            float4 a1 = *(const float4*)&As[k][ty * 8 + 4];
            float4 b0 = *(const float4*)&Bs[k][tx * 8];
            float4 b1 = *(const float4*)&Bs[k][tx * 8 + 4];
            float ar[8] = {a0.x, a0.y, a0.z, a0.w, a1.x, a1.y, a1.z, a1.w};
            float br[8] = {b0.x, b0.y, b0.z, b0.w, b1.x, b1.y, b1.z, b1.w};
#pragma unroll
            for (int i = 0; i < 8; ++i)
#pragma unroll
                for (int j = 0; j < 8; ++j)
                    acc[i][j] = fmaf(ar[i], br[j], acc[i][j]);
        }
        __syncthreads();
    }

    float bb[8];
#pragma unroll
    for (int j = 0; j < 8; ++j) bb[j] = bias[bn + tx * 8 + j];
#pragma unroll
    for (int i = 0; i < 8; ++i) {
        size_t rbase = (size_t)(bm + ty * 8 + i) * 384 + bn + tx * 8;
        float4 v0 = make_float4(acc[i][0] + bb[0], acc[i][1] + bb[1],
                                acc[i][2] + bb[2], acc[i][3] + bb[3]);
        float4 v1 = make_float4(acc[i][4] + bb[4], acc[i][5] + bb[5],
                                acc[i][6] + bb[6], acc[i][7] + bb[7]);
        *(float4*)(g_gi + rbase)     = v0;
        *(float4*)(g_gi + rbase + 4) = v1;
    }
}

// ===========================================================================
// Kernel 2: persistent GRU. Block owns 32 batch rows for all 50 steps.
// ===========================================================================
#define GRU_SMEM_BYTES ((3 * 128 * 128 + 32 * 128) * 4)

#define GRU_ACC4(A, W) \
    A[r][0] = fmaf(hv, W.x, A[r][0]); A[r][1] = fmaf(hv, W.y, A[r][1]); \
    A[r][2] = fmaf(hv, W.z, A[r][2]); A[r][3] = fmaf(hv, W.w, A[r][3]);

#define GRU_COMP(CC, GRc, GZc, GNc, HOc, HNc) {                           \
    float rr = fsigmoid(GRc + aR[r][CC] + bR[CC]);                        \
    float zz = fsigmoid(GZc + aZ[r][CC] + bZ[CC]);                        \
    float nn = ftanh(GNc + rr * (aN[r][CC] + bN[CC]));                    \
    HNc = fmaf(zz, HOc - nn, nn); }

__global__ void __launch_bounds__(256) gru_kernel(const float* __restrict__ Whh,
                                                  const float* __restrict__ bhh)
{
    extern __shared__ float sm[];
    float* WT = sm;                   // [g*128+k][u]
    float* hs = sm + 3 * 128 * 128;   // [32][128]
    const int tid = threadIdx.x;

    for (int idx = tid; idx < 3 * 128 * 128; idx += 256) {
        int row = idx >> 7;
        int k = idx & 127;
        int g = row >> 7, u = row & 127;
        WT[(g * 128 + k) * 128 + u] = Whh[idx];
    }
    for (int idx = tid; idx < 32 * 128; idx += 256) hs[idx] = 0.0f;
    __syncthreads();

    const int ug = tid & 31;
    const int rg = tid >> 5;
    const int row0 = blockIdx.x * 32;

    float bR[4], bZ[4], bN[4];
#pragma unroll
    for (int c = 0; c < 4; ++c) {
        bR[c] = bhh[ug * 4 + c];
        bZ[c] = bhh[128 + ug * 4 + c];
        bN[c] = bhh[256 + ug * 4 + c];
    }
    const float4* Wr4 = (const float4*)(WT);
    const float4* Wz4 = (const float4*)(WT + 128 * 128);
    const float4* Wn4 = (const float4*)(WT + 2 * 128 * 128);

    for (int t = 0; t < NENC; ++t) {
        float aR[4][4], aZ[4][4], aN[4][4];
#pragma unroll
        for (int r = 0; r < 4; ++r)
#pragma unroll
            for (int c = 0; c < 4; ++c) { aR[r][c] = 0.f; aZ[r][c] = 0.f; aN[r][c] = 0.f; }

#pragma unroll 2
        for (int k = 0; k < 128; ++k) {
            float4 wr = Wr4[k * 32 + ug];
            float4 wz = Wz4[k * 32 + ug];
            float4 wn = Wn4[k * 32 + ug];
#pragma unroll
            for (int r = 0; r < 4; ++r) {
                float hv = hs[(rg * 4 + r) * 128 + k];
                GRU_ACC4(aR, wr)
                GRU_ACC4(aZ, wz)
                GRU_ACC4(aN, wn)
            }
        }
        __syncthreads();

        const float* gbase = g_gi + ((size_t)t * BATCH + row0) * 384;
#pragma unroll
        for (int r = 0; r < 4; ++r) {
            int lr = rg * 4 + r;
            const float4* gf = (const float4*)(gbase + (size_t)lr * 384);
            float4 giR = gf[ug];
            float4 giZ = gf[32 + ug];
            float4 giN = gf[64 + ug];
            float4 hold = ((const float4*)(hs + lr * 128))[ug];
            float4 hn;
            GRU_COMP(0, giR.x, giZ.x, giN.x, hold.x, hn.x)
            GRU_COMP(1, giR.y, giZ.y, giN.y, hold.y, hn.y)
            GRU_COMP(2, giR.z, giZ.z, giN.z, hold.z, hn.z)
            GRU_COMP(3, giR.w, giZ.w, giN.w, hold.w, hn.w)
            ((float4*)(hs + lr * 128))[ug] = hn;
        }
        __syncthreads();
    }

    for (int idx = tid; idx < 32 * 128; idx += 256)
        g_hlast[(size_t)row0 * 128 + idx] = hs[idx];
}

// ===========================================================================
// Kernel 3: z0 head (one thread per batch row)
// ===========================================================================
__global__ void z0_kernel(const float* __restrict__ eps,
                          const float* __restrict__ meanW, const float* __restrict__ meanb,
                          const float* __restrict__ logW, const float* __restrict__ logb,
                          float* __restrict__ omean, float* __restrict__ ologv)
{
    const int b = blockIdx.x * 128 + threadIdx.x;
    const float4* h4 = (const float4*)(g_hlast + (size_t)b * 128);
    float m0 = 0.f, m1 = 0.f, m2 = 0.f, l0 = 0.f, l1 = 0.f, l2 = 0.f;
#pragma unroll
    for (int i = 0; i < 32; ++i) {
        float4 h = h4[i];
        float4 w;
        w = ((const float4*)meanW)[i];
        m0 = fmaf(h.x, w.x, fmaf(h.y, w.y, fmaf(h.z, w.z, fmaf(h.w, w.w, m0))));
        w = ((const float4*)(meanW + 128))[i];
        m1 = fmaf(h.x, w.x, fmaf(h.y, w.y, fmaf(h.z, w.z, fmaf(h.w, w.w, m1))));
        w = ((const float4*)(meanW + 256))[i];
        m2 = fmaf(h.x, w.x, fmaf(h.y, w.y, fmaf(h.z, w.z, fmaf(h.w, w.w, m2))));
        w = ((const float4*)logW)[i];
        l0 = fmaf(h.x, w.x, fmaf(h.y, w.y, fmaf(h.z, w.z, fmaf(h.w, w.w, l0))));
        w = ((const float4*)(logW + 128))[i];
        l1 = fmaf(h.x, w.x, fmaf(h.y, w.y, fmaf(h.z, w.z, fmaf(h.w, w.w, l1))));
        w = ((const float4*)(logW + 256))[i];
        l2 = fmaf(h.x, w.x, fmaf(h.y, w.y, fmaf(h.z, w.z, fmaf(h.w, w.w, l2))));
    }
    m0 += meanb[0]; m1 += meanb[1]; m2 += meanb[2];
    l0 += logb[0];  l1 += logb[1];  l2 += logb[2];
    omean[b * 3 + 0] = m0; omean[b * 3 + 1] = m1; omean[b * 3 + 2] = m2;
    ologv[b * 3 + 0] = l0; ologv[b * 3 + 1] = l1; ologv[b * 3 + 2] = l2;
    g_z0[b * 3 + 0] = fmaf(eps[b * 3 + 0], expf(0.5f * l0), m0);
    g_z0[b * 3 + 1] = fmaf(eps[b * 3 + 1], expf(0.5f * l1), m1);
    g_z0[b * 3 + 2] = fmaf(eps[b * 3 + 2], expf(0.5f * l2), m2);
}

// ===========================================================================
// Kernel 4: RK4 ODE + fused decoder.
// 256 thr/block, 32 elems/block, grid 128 -> 1024 warps, 2/SMSP on 128 SMs.
// 8 threads/element: qj in [0,4) owns 25(->28) j's, qk in [0,2) owns k-half
// (padded 52). Cross-qk reduce via shfl_xor(4); cross-qj via shfl_xor(2,1).
// ===========================================================================
// smem float offsets
#define O_W1B 0        // 100 float4 (W1 row, b1)
#define O_W3  400      // 112 float4 (qj-padded W3 cols)
#define O_DW1 848      // 64 float4 (decW1 row, decb1)
#define O_W2  1104     // 104*112: [k][pj] = W2[qj*25+jj][k], pads 0
#define O_DW2 12752    // 64*64:   [k][o]  = decW2[o][k]
#define O_B2P 16848    // 112 padded b2
#define O_DB2 16960    // 64
#define O_TS  17024    // 200
#define O_H1  17224    // 32*104 (k-pad 100..103 zeroed)
#define O_HD  20552    // 32*64
#define ODE_SMEM_BYTES (22600 * 4)

__device__ __forceinline__ void dynf(float zx, float zy, float zz,
    float& ox, float& oy, float& oz,
    const float4* sW1b, const float4* sW2T4, const float4* sW3,
    const float4* sB2p4, float* myH1, const float* myH1k,
    int qj, int qk, float b3x, float b3y, float b3z)
{
    // ---- layer 1: qj's 25 j's split ~13/12 across qk (jj=12 dup, benign) ----
#pragma unroll
    for (int t = 0; t < 13; ++t) {
        int jj = qk * 12 + t;
        float4 w = sW1b[qj * 25 + jj];
        myH1[qj * 25 + jj] = ftanh(fmaf(zx, w.x, fmaf(zy, w.y, fmaf(zz, w.z, w.w))));
    }
    __syncwarp();
    // ---- layer 2: partial sums over this thread's 52-k half ----
    float4 a[7];
#pragma unroll
    for (int i = 0; i < 7; ++i) {
        float4 bz = sB2p4[qj * 7 + i];
        a[i] = qk ? make_float4(0.f, 0.f, 0.f, 0.f) : bz;
    }
    const int kbase = qk * 52;
#pragma unroll 2
    for (int kk = 0; kk < 13; ++kk) {
        float4 hv4 = *(const float4*)(myH1k + kk * 4);
        const float4* w0 = sW2T4 + (kbase + kk * 4) * 28 + qj * 7;
        float hvs[4] = {hv4.x, hv4.y, hv4.z, hv4.w};
#pragma unroll
        for (int c = 0; c < 4; ++c) {
            const float4* w = w0 + c * 28;
#pragma unroll
            for (int i = 0; i < 7; ++i) {
                float4 ww = w[i];
                a[i].x = fmaf(hvs[c], ww.x, a[i].x);
                a[i].y = fmaf(hvs[c], ww.y, a[i].y);
                a[i].z = fmaf(hvs[c], ww.z, a[i].z);
                a[i].w = fmaf(hvs[c], ww.w, a[i].w);
            }
        }
    }
    __syncwarp();
    // ---- cross-qk reduce of the 28 partial sums ----
#pragma unroll
    for (int i = 0; i < 7; ++i) {
        a[i].x += __shfl_xor_sync(0xffffffffu, a[i].x, 4);
        a[i].y += __shfl_xor_sync(0xffffffffu, a[i].y, 4);
        a[i].z += __shfl_xor_sync(0xffffffffu, a[i].z, 4);
        a[i].w += __shfl_xor_sync(0xffffffffu, a[i].w, 4);
    }
    // ---- layer 3: split i-range across qk (compile-time indices) ----
    float px = 0.f, py = 0.f, pz = 0.f;
    if (qk == 0) {
#pragma unroll
        for (int i = 0; i < 4; ++i) {
            float av[4] = {a[i].x, a[i].y, a[i].z, a[i].w};
#pragma unroll
            for (int c = 0; c < 4; ++c) {
                float h2 = ftanh(av[c]);
                float4 w3 = sW3[qj * 28 + i * 4 + c];
                px = fmaf(h2, w3.x, px);
                py = fmaf(h2, w3.y, py);
                pz = fmaf(h2, w3.z, pz);
            }
        }
    } else {
#pragma unroll
        for (int i = 4; i < 7; ++i) {
            float av[4] = {a[i].x, a[i].y, a[i].z, a[i].w};
#pragma unroll
            for (int c = 0; c < 4; ++c) {
                float h2 = ftanh(av[c]);
                float4 w3 = sW3[qj * 28 + i * 4 + c];
                px = fmaf(h2, w3.x, px);
                py = fmaf(h2, w3.y, py);
                pz = fmaf(h2, w3.z, pz);
            }
        }
    }
    __syncwarp();
    // ---- reduce px/py/pz across the element's 8 lanes ----
    px += __shfl_xor_sync(0xffffffffu, px, 4);
    py += __shfl_xor_sync(0xffffffffu, py, 4);
    pz += __shfl_xor_sync(0xffffffffu, pz, 4);
    px += __shfl_xor_sync(0xffffffffu, px, 2);
    py += __shfl_xor_sync(0xffffffffu, py, 2);
    pz += __shfl_xor_sync(0xffffffffu, pz, 2);
    px += __shfl_xor_sync(0xffffffffu, px, 1);
    py += __shfl_xor_sync(0xffffffffu, py, 1);
    pz += __shfl_xor_sync(0xffffffffu, pz, 1);
    ox = px + b3x; oy = py + b3y; oz = pz + b3z;
}

__global__ void __launch_bounds__(256) ode_kernel(
    const float* __restrict__ dynW1, const float* __restrict__ dynb1,
    const float* __restrict__ dynW2, const float* __restrict__ dynb2,
    const float* __restrict__ dynW3, const float* __restrict__ dynb3,
    const float* __restrict__ decW1, const float* __restrict__ decb1,
    const float* __restrict__ decW2, const float* __restrict__ decb2,
    const float* __restrict__ tsg,
    float* __restrict__ recon, float* __restrict__ traj)
{
    extern __shared__ float sm[];
    float4* sW1b  = (float4*)(sm + O_W1B);
    float4* sW3   = (float4*)(sm + O_W3);
    float4* sDW1  = (float4*)(sm + O_DW1);
    float*  sW2f  = sm + O_W2;
    float*  sDW2f = sm + O_DW2;
    float*  sB2p  = sm + O_B2P;
    float*  sDB2  = sm + O_DB2;
    float*  sTS   = sm + O_TS;

    const int tid = threadIdx.x;
    // ---- stage weights ----
    for (int i = tid; i < 100; i += 256)
        sW1b[i] = make_float4(dynW1[i * 3], dynW1[i * 3 + 1], dynW1[i * 3 + 2], dynb1[i]);
    for (int i = tid; i < 112; i += 256) {
        int ch = i / 28, off = i % 28;
        if (off < 25) {
            int rj = ch * 25 + off;
            sW3[i] = make_float4(dynW3[rj], dynW3[100 + rj], dynW3[200 + rj], 0.f);
            sB2p[i] = dynb2[rj];
        } else {
            sW3[i] = make_float4(0.f, 0.f, 0.f, 0.f);
            sB2p[i] = 0.f;
        }
    }
    for (int i = tid; i < 64; i += 256) {
        sDW1[i] = make_float4(decW1[i * 3], decW1[i * 3 + 1], decW1[i * 3 + 2], decb1[i]);
        sDB2[i] = decb2[i];
    }
    for (int idx = tid; idx < 104 * 112; idx += 256) {
        int k = idx / 112, p = idx % 112;
        int ch = p / 28, off = p % 28;
        sW2f[idx] = (off < 25 && k < 100) ? dynW2[(ch * 25 + off) * 100 + k] : 0.f;
    }
    for (int idx = tid; idx < 64 * 64; idx += 256) {
        int k = idx >> 6, oo = idx & 63;
        sDW2f[idx] = decW2[oo * 64 + k];
    }
    for (int i = tid; i < 200; i += 256) sTS[i] = tsg[i];
    for (int i = tid; i < 32 * 4; i += 256) {
        int e = i >> 2, p = i & 3;
        sm[O_H1 + e * 104 + 100 + p] = 0.f;   // k-pads stay zero forever
    }
    __syncthreads();

    const int q8 = tid & 7;
    const int qj = q8 & 3;
    const int qk = q8 >> 2;
    const int e  = tid >> 3;
    const int b  = blockIdx.x * 32 + e;
    float* myH1        = sm + O_H1 + e * 104;
    const float* myH1k = myH1 + qk * 52;
    float* myHD        = sm + O_HD + e * 64;
    const float4* sW2T4  = (const float4*)sW2f;
    const float4* sDW2_4 = (const float4*)sDW2f;
    const float4* sB2p4  = (const float4*)sB2p;
    const float4* sDB2_4 = (const float4*)sDB2;

    const float b3x = dynb3[0], b3y = dynb3[1], b3z = dynb3[2];

    float zx = g_z0[b * 3 + 0];
    float zy = g_z0[b * 3 + 1];
    float zz = g_z0[b * 3 + 2];

    for (int t = 0; t < T_STEPS; ++t) {
        if (q8 == 0) {
            size_t to = ((size_t)t * BATCH + b) * 3;
            traj[to] = zx; traj[to + 1] = zy; traj[to + 2] = zz;
        }
        // ---- decoder: q8 owns 8 hidden units then 8 outputs ----
        {
#pragma unroll
            for (int j = 0; j < 8; ++j) {
                float4 w = sDW1[q8 * 8 + j];
                float v = fmaf(zx, w.x, fmaf(zy, w.y, fmaf(zz, w.z, w.w)));
                myHD[q8 * 8 + j] = fmaxf(v, 0.f);
            }
            __syncwarp();
            float4 od0 = sDB2_4[q8 * 2];
            float4 od1 = sDB2_4[q8 * 2 + 1];
#pragma unroll 4
            for (int kk = 0; kk < 16; ++kk) {
                float4 hv4 = *(const float4*)(myHD + kk * 4);
                float hvs[4] = {hv4.x, hv4.y, hv4.z, hv4.w};
#pragma unroll
                for (int c = 0; c < 4; ++c) {
                    const float4* w = sDW2_4 + (kk * 4 + c) * 16 + q8 * 2;
                    float4 w0 = w[0], w1 = w[1];
                    od0.x = fmaf(hvs[c], w0.x, od0.x);
                    od0.y = fmaf(hvs[c], w0.y, od0.y);
                    od0.z = fmaf(hvs[c], w0.z, od0.z);
                    od0.w = fmaf(hvs[c], w0.w, od0.w);
                    od1.x = fmaf(hvs[c], w1.x, od1.x);
                    od1.y = fmaf(hvs[c], w1.y, od1.y);
                    od1.z = fmaf(hvs[c], w1.z, od1.z);
                    od1.w = fmaf(hvs[c], w1.w, od1.w);
                }
            }
            __syncwarp();
            float4* dst = (float4*)(recon + ((size_t)t * BATCH + b) * 64 + q8 * 8);
            dst[0] = od0; dst[1] = od1;
        }
        // ---- RK4 step ----
        if (t < T_STEPS - 1) {
            float dt = sTS[t + 1] - sTS[t];
            float hh = 0.5f * dt;
            float k1x, k1y, k1z, k2x, k2y, k2z, k3x, k3y, k3z, k4x, k4y, k4z;
            dynf(zx, zy, zz, k1x, k1y, k1z, sW1b, sW2T4, sW3, sB2p4, myH1, myH1k, qj, qk, b3x, b3y, b3z);
            dynf(fmaf(hh, k1x, zx), fmaf(hh, k1y, zy), fmaf(hh, k1z, zz),
                 k2x, k2y, k2z, sW1b, sW2T4, sW3, sB2p4, myH1, myH1k, qj, qk, b3x, b3y, b3z);
            dynf(fmaf(hh, k2x, zx), fmaf(hh, k2y, zy), fmaf(hh, k2z, zz),
                 k3x, k3y, k3z, sW1b, sW2T4, sW3, sB2p4, myH1, myH1k, qj, qk, b3x, b3y, b3z);
            dynf(fmaf(dt, k3x, zx), fmaf(dt, k3y, zy), fmaf(dt, k3z, zz),
                 k4x, k4y, k4z, sW1b, sW2T4, sW3, sB2p4, myH1, myH1k, qj, qk, b3x, b3y, b3z);
            float s = dt * (1.0f / 6.0f);
            zx += s * (k1x + 2.0f * (k2x + k3x) + k4x);
            zy += s * (k1y + 2.0f * (k2y + k3y) + k4y);
            zz += s * (k1z + 2.0f * (k2z + k3z) + k4z);
        }
    }
}

// ===========================================================================
extern "C" void kernel_launch(void* const* d_in, const int* in_sizes, int n_in,
                              void* d_out, int out_size) {
    (void)in_sizes; (void)n_in; (void)out_size;
    const float* obs   = (const float*)d_in[0];
    const float* eps   = (const float*)d_in[1];
    const float* Wih   = (const float*)d_in[2];
    const float* Whh   = (const float*)d_in[3];
    const float* bih   = (const float*)d_in[4];
    const float* bhh   = (const float*)d_in[5];
    const float* meanW = (const float*)d_in[6];
    const float* meanb = (const float*)d_in[7];
    const float* logW  = (const float*)d_in[8];
    const float* logb  = (const float*)d_in[9];
    const float* dynW1 = (const float*)d_in[10];
    const float* dynb1 = (const float*)d_in[11];
    const float* dynW2 = (const float*)d_in[12];
    const float* dynb2 = (const float*)d_in[13];
    const float* dynW3 = (const float*)d_in[14];
    const float* dynb3 = (const float*)d_in[15];
    const float* decW1 = (const float*)d_in[16];
    const float* decb1 = (const float*)d_in[17];
    const float* decW2 = (const float*)d_in[18];
    const float* decb2 = (const float*)d_in[19];
    const float* ts    = (const float*)d_in[20];

    float* out   = (float*)d_out;
    float* recon = out;                      // [200,4096,64]
    float* omean = out + RECON_ELEMS;        // [4096,3]
    float* ologv = omean + ZM_ELEMS;         // [4096,3]
    float* traj  = ologv + ZM_ELEMS;         // [200,4096,3]

    cudaFuncSetAttribute(gru_kernel, cudaFuncAttributeMaxDynamicSharedMemorySize, GRU_SMEM_BYTES);
    cudaFuncSetAttribute(ode_kernel, cudaFuncAttributeMaxDynamicSharedMemorySize, ODE_SMEM_BYTES);

    dim3 g1(1600, 3);
    gi_gemm_kernel<<<g1, 256>>>(obs, Wih, bih);
    gru_kernel<<<128, 256, GRU_SMEM_BYTES>>>(Whh, bhh);
    z0_kernel<<<32, 128>>>(eps, meanW, meanb, logW, logb, omean, ologv);
    ode_kernel<<<128, 256, ODE_SMEM_BYTES>>>(dynW1, dynb1, dynW2, dynb2, dynW3, dynb3,
                                             decW1, decb1, decW2, decb2, ts, recon, traj);
}

// round 6
// speedup vs baseline: 2.1808x; 2.1808x over previous
#include <cuda_runtime.h>
#include <cuda_bf16.h>
#include <cstddef>
#include <cstdint>

#define T_STEPS 200
#define BATCH   4096
#define OBS     64
#define HID     128
#define NENC    50

#define RECON_ELEMS ((size_t)T_STEPS * BATCH * OBS)
#define ZM_ELEMS    ((size_t)BATCH * 3)

// Scratch (static device arrays; no runtime allocation)
__device__ float g_gi[(size_t)NENC * BATCH * 3 * HID];
__device__ float g_hlast[(size_t)BATCH * HID];
__device__ float g_z0[(size_t)BATCH * 3];

__device__ __forceinline__ float fsigmoid(float x) {
    return __fdividef(1.0f, 1.0f + __expf(-x));
}
__device__ __forceinline__ float ftanh(float x) {
    return 1.0f - __fdividef(2.0f, __expf(2.0f * x) + 1.0f);
}

// ---- packed fp32x2 helpers (Blackwell) ----
__device__ __forceinline__ void fma2(unsigned long long& d, unsigned long long a,
                                     unsigned long long b) {
    asm("fma.rn.f32x2 %0, %1, %2, %0;" : "+l"(d) : "l"(a), "l"(b));
}
__device__ __forceinline__ float2 unpack2(unsigned long long v) {
    float2 r;
    asm("mov.b64 {%0, %1}, %2;" : "=f"(r.x), "=f"(r.y) : "l"(v));
    return r;
}

// ===========================================================================
// Kernel 1: GI = obs[:50] @ Wih^T + bih  (NT SGEMM M=204800, N=384, K=64)
// ===========================================================================
__global__ void gi_gemm_kernel(const float* __restrict__ A,
                               const float* __restrict__ B,
                               const float* __restrict__ bias)
{
    __shared__ float As[16][128];
    __shared__ float Bs[16][128];
    const int tid = threadIdx.x;
    const int bm = blockIdx.x * 128;
    const int bn = blockIdx.y * 128;
    const int tx = tid & 15;
    const int ty = tid >> 4;

    float acc[8][8];
#pragma unroll
    for (int i = 0; i < 8; ++i)
#pragma unroll
        for (int j = 0; j < 8; ++j) acc[i][j] = 0.0f;

    for (int kk = 0; kk < 64; kk += 16) {
#pragma unroll
        for (int l = 0; l < 2; ++l) {
            int fi = tid + 256 * l;
            int row = fi >> 2;
            int kq = fi & 3;
            float4 va = *(const float4*)(A + (size_t)(bm + row) * 64 + kk + kq * 4);
            As[kq * 4 + 0][row] = va.x; As[kq * 4 + 1][row] = va.y;
            As[kq * 4 + 2][row] = va.z; As[kq * 4 + 3][row] = va.w;
            float4 vb = *(const float4*)(B + (size_t)(bn + row) * 64 + kk + kq * 4);
            Bs[kq * 4 + 0][row] = vb.x; Bs[kq * 4 + 1][row] = vb.y;
            Bs[kq * 4 + 2][row] = vb.z; Bs[kq * 4 + 3][row] = vb.w;
        }
        __syncthreads();
#pragma unroll
        for (int k = 0; k < 16; ++k) {
            float4 a0 = *(const float4*)&As[k][ty * 8];
            float4 a1 = *(const float4*)&As[k][ty * 8 + 4];
            float4 b0 = *(const float4*)&Bs[k][tx * 8];
            float4 b1 = *(const float4*)&Bs[k][tx * 8 + 4];
            float ar[8] = {a0.x, a0.y, a0.z, a0.w, a1.x, a1.y, a1.z, a1.w};
            float br[8] = {b0.x, b0.y, b0.z, b0.w, b1.x, b1.y, b1.z, b1.w};
#pragma unroll
            for (int i = 0; i < 8; ++i)
#pragma unroll
                for (int j = 0; j < 8; ++j)
                    acc[i][j] = fmaf(ar[i], br[j], acc[i][j]);
        }
        __syncthreads();
    }

    float bb[8];
#pragma unroll
    for (int j = 0; j < 8; ++j) bb[j] = bias[bn + tx * 8 + j];
#pragma unroll
    for (int i = 0; i < 8; ++i) {
        size_t rbase = (size_t)(bm + ty * 8 + i) * 384 + bn + tx * 8;
        float4 v0 = make_float4(acc[i][0] + bb[0], acc[i][1] + bb[1],
                                acc[i][2] + bb[2], acc[i][3] + bb[3]);
        float4 v1 = make_float4(acc[i][4] + bb[4], acc[i][5] + bb[5],
                                acc[i][6] + bb[6], acc[i][7] + bb[7]);
        *(float4*)(g_gi + rbase)     = v0;
        *(float4*)(g_gi + rbase + 4) = v1;
    }
}

// ===========================================================================
// Kernel 2: persistent GRU. Block owns 32 batch rows for all 50 steps.
// ===========================================================================
#define GRU_SMEM_BYTES ((3 * 128 * 128 + 32 * 128) * 4)

#define GRU_ACC4(A, W) \
    A[r][0] = fmaf(hv, W.x, A[r][0]); A[r][1] = fmaf(hv, W.y, A[r][1]); \
    A[r][2] = fmaf(hv, W.z, A[r][2]); A[r][3] = fmaf(hv, W.w, A[r][3]);

#define GRU_COMP(CC, GRc, GZc, GNc, HOc, HNc) {                           \
    float rr = fsigmoid(GRc + aR[r][CC] + bR[CC]);                        \
    float zz = fsigmoid(GZc + aZ[r][CC] + bZ[CC]);                        \
    float nn = ftanh(GNc + rr * (aN[r][CC] + bN[CC]));                    \
    HNc = fmaf(zz, HOc - nn, nn); }

__global__ void __launch_bounds__(256) gru_kernel(const float* __restrict__ Whh,
                                                  const float* __restrict__ bhh)
{
    extern __shared__ float sm[];
    float* WT = sm;                   // [g*128+k][u]
    float* hs = sm + 3 * 128 * 128;   // [32][128]
    const int tid = threadIdx.x;

    for (int idx = tid; idx < 3 * 128 * 128; idx += 256) {
        int row = idx >> 7;
        int k = idx & 127;
        int g = row >> 7, u = row & 127;
        WT[(g * 128 + k) * 128 + u] = Whh[idx];
    }
    for (int idx = tid; idx < 32 * 128; idx += 256) hs[idx] = 0.0f;
    __syncthreads();

    const int ug = tid & 31;
    const int rg = tid >> 5;
    const int row0 = blockIdx.x * 32;

    float bR[4], bZ[4], bN[4];
#pragma unroll
    for (int c = 0; c < 4; ++c) {
        bR[c] = bhh[ug * 4 + c];
        bZ[c] = bhh[128 + ug * 4 + c];
        bN[c] = bhh[256 + ug * 4 + c];
    }
    const float4* Wr4 = (const float4*)(WT);
    const float4* Wz4 = (const float4*)(WT + 128 * 128);
    const float4* Wn4 = (const float4*)(WT + 2 * 128 * 128);

    for (int t = 0; t < NENC; ++t) {
        float aR[4][4], aZ[4][4], aN[4][4];
#pragma unroll
        for (int r = 0; r < 4; ++r)
#pragma unroll
            for (int c = 0; c < 4; ++c) { aR[r][c] = 0.f; aZ[r][c] = 0.f; aN[r][c] = 0.f; }

#pragma unroll 2
        for (int k = 0; k < 128; ++k) {
            float4 wr = Wr4[k * 32 + ug];
            float4 wz = Wz4[k * 32 + ug];
            float4 wn = Wn4[k * 32 + ug];
#pragma unroll
            for (int r = 0; r < 4; ++r) {
                float hv = hs[(rg * 4 + r) * 128 + k];
                GRU_ACC4(aR, wr)
                GRU_ACC4(aZ, wz)
                GRU_ACC4(aN, wn)
            }
        }
        __syncthreads();

        const float* gbase = g_gi + ((size_t)t * BATCH + row0) * 384;
#pragma unroll
        for (int r = 0; r < 4; ++r) {
            int lr = rg * 4 + r;
            const float4* gf = (const float4*)(gbase + (size_t)lr * 384);
            float4 giR = gf[ug];
            float4 giZ = gf[32 + ug];
            float4 giN = gf[64 + ug];
            float4 hold = ((const float4*)(hs + lr * 128))[ug];
            float4 hn;
            GRU_COMP(0, giR.x, giZ.x, giN.x, hold.x, hn.x)
            GRU_COMP(1, giR.y, giZ.y, giN.y, hold.y, hn.y)
            GRU_COMP(2, giR.z, giZ.z, giN.z, hold.z, hn.z)
            GRU_COMP(3, giR.w, giZ.w, giN.w, hold.w, hn.w)
            ((float4*)(hs + lr * 128))[ug] = hn;
        }
        __syncthreads();
    }

    for (int idx = tid; idx < 32 * 128; idx += 256)
        g_hlast[(size_t)row0 * 128 + idx] = hs[idx];
}

// ===========================================================================
// Kernel 3: z0 head (one thread per batch row)
// ===========================================================================
__global__ void z0_kernel(const float* __restrict__ eps,
                          const float* __restrict__ meanW, const float* __restrict__ meanb,
                          const float* __restrict__ logW, const float* __restrict__ logb,
                          float* __restrict__ omean, float* __restrict__ ologv)
{
    const int b = blockIdx.x * 128 + threadIdx.x;
    const float4* h4 = (const float4*)(g_hlast + (size_t)b * 128);
    float m0 = 0.f, m1 = 0.f, m2 = 0.f, l0 = 0.f, l1 = 0.f, l2 = 0.f;
#pragma unroll
    for (int i = 0; i < 32; ++i) {
        float4 h = h4[i];
        float4 w;
        w = ((const float4*)meanW)[i];
        m0 = fmaf(h.x, w.x, fmaf(h.y, w.y, fmaf(h.z, w.z, fmaf(h.w, w.w, m0))));
        w = ((const float4*)(meanW + 128))[i];
        m1 = fmaf(h.x, w.x, fmaf(h.y, w.y, fmaf(h.z, w.z, fmaf(h.w, w.w, m1))));
        w = ((const float4*)(meanW + 256))[i];
        m2 = fmaf(h.x, w.x, fmaf(h.y, w.y, fmaf(h.z, w.z, fmaf(h.w, w.w, m2))));
        w = ((const float4*)logW)[i];
        l0 = fmaf(h.x, w.x, fmaf(h.y, w.y, fmaf(h.z, w.z, fmaf(h.w, w.w, l0))));
        w = ((const float4*)(logW + 128))[i];
        l1 = fmaf(h.x, w.x, fmaf(h.y, w.y, fmaf(h.z, w.z, fmaf(h.w, w.w, l1))));
        w = ((const float4*)(logW + 256))[i];
        l2 = fmaf(h.x, w.x, fmaf(h.y, w.y, fmaf(h.z, w.z, fmaf(h.w, w.w, l2))));
    }
    m0 += meanb[0]; m1 += meanb[1]; m2 += meanb[2];
    l0 += logb[0];  l1 += logb[1];  l2 += logb[2];
    omean[b * 3 + 0] = m0; omean[b * 3 + 1] = m1; omean[b * 3 + 2] = m2;
    ologv[b * 3 + 0] = l0; ologv[b * 3 + 1] = l1; ologv[b * 3 + 2] = l2;
    g_z0[b * 3 + 0] = fmaf(eps[b * 3 + 0], expf(0.5f * l0), m0);
    g_z0[b * 3 + 1] = fmaf(eps[b * 3 + 1], expf(0.5f * l1), m1);
    g_z0[b * 3 + 2] = fmaf(eps[b * 3 + 2], expf(0.5f * l2), m2);
}

// ===========================================================================
// Kernel 4: RK4 ODE + fused decoder, GEMM-structured with f32x2 packed FMA.
// 256 thr/block, E=32 elems/block, grid=128.
// Layer2 tile: etg=tid&15 (elem pair), jtg=tid>>4 (7 j's). Acts H1T[k][e],
// weights pre-duplicated {w,w} in smem so accumulators pack the elem pair.
// ===========================================================================
// smem float offsets
#define O_W1B   0        // 112 float4 (W1 row, b1); pads 0
#define O_W3    448      // 112 float4 (W3 col, 0); pads 0
#define O_B2D   896      // 112 float2 {b2,b2}; pads 0
#define O_DW1   1120     // 64 float4 (decW1 row, decb1)
#define O_DB2D  1376     // 64 float2 {b,b}
#define O_TS    1504     // 200 (+pad)
#define O_ZS0   1712     // 32 float4
#define O_ZS1   1840     // 32 float4
#define O_PARTX 1968     // [16 jtg][32 e]
#define O_PARTY 2480
#define O_PARTZ 2992
#define O_H1T   3504     // [112 j][32 e]
#define O_HDT   7088     // [64 h][32 e]
#define O_W2D   9136     // [104 k][16 jtg * 16] packed {w,w} per j, slot pad 0
#define O_DW2D  35760    // [64 k][16 og * 8] packed {w,w} per o
#define ODE_SMEM_FLOATS 43952
#define ODE_SMEM_BYTES  (ODE_SMEM_FLOATS * 4)

// dynf stage: reads zin (float4[32]), writes partX/Y/Z[jtg][e]. 2 internal syncs.
__device__ __forceinline__ void dyn_stage(float* sm, const float4* zin,
                                          int etg, int jtg, int e0)
{
    // ---- layer 1: j = jtg*7 + jj, elems e0,e0+1 ----
    {
        float4 za = zin[e0];
        float4 zb = zin[e0 + 1];
        const float4* w1 = (const float4*)(sm + O_W1B);
#pragma unroll
        for (int jj = 0; jj < 7; ++jj) {
            int j = jtg * 7 + jj;
            float4 w = w1[j];
            float p0 = fmaf(za.x, w.x, fmaf(za.y, w.y, fmaf(za.z, w.z, w.w)));
            float p1 = fmaf(zb.x, w.x, fmaf(zb.y, w.y, fmaf(zb.z, w.z, w.w)));
            *(float2*)(sm + O_H1T + j * 32 + e0) = make_float2(ftanh(p0), ftanh(p1));
        }
    }
    __syncthreads();
    // ---- layer 2: packed GEMM over k ----
    unsigned long long acc[7];
#pragma unroll
    for (int jj = 0; jj < 7; ++jj)
        acc[jj] = *(const unsigned long long*)(sm + O_B2D + (jtg * 7 + jj) * 2);
    {
        const float* abase = sm + O_H1T + e0;
        const float* wbase = sm + O_W2D + jtg * 16;
#pragma unroll 4
        for (int k = 0; k < 104; ++k) {
            unsigned long long a = *(const unsigned long long*)(abase + k * 32);
            const float* wr = wbase + k * 256;
            ulonglong2 wA = *(const ulonglong2*)(wr);
            ulonglong2 wB = *(const ulonglong2*)(wr + 4);
            ulonglong2 wC = *(const ulonglong2*)(wr + 8);
            unsigned long long wD = *(const unsigned long long*)(wr + 12);
            fma2(acc[0], a, wA.x);
            fma2(acc[1], a, wA.y);
            fma2(acc[2], a, wB.x);
            fma2(acc[3], a, wB.y);
            fma2(acc[4], a, wC.x);
            fma2(acc[5], a, wC.y);
            fma2(acc[6], a, wD);
        }
    }
    // ---- layer 3: tanh + W3 partials ----
    {
        float px0 = 0.f, py0 = 0.f, pz0 = 0.f;
        float px1 = 0.f, py1 = 0.f, pz1 = 0.f;
        const float4* w3 = (const float4*)(sm + O_W3);
#pragma unroll
        for (int jj = 0; jj < 7; ++jj) {
            float2 h = unpack2(acc[jj]);
            float t0 = ftanh(h.x);
            float t1 = ftanh(h.y);
            float4 w = w3[jtg * 7 + jj];
            px0 = fmaf(t0, w.x, px0); py0 = fmaf(t0, w.y, py0); pz0 = fmaf(t0, w.z, pz0);
            px1 = fmaf(t1, w.x, px1); py1 = fmaf(t1, w.y, py1); pz1 = fmaf(t1, w.z, pz1);
        }
        *(float2*)(sm + O_PARTX + jtg * 32 + e0) = make_float2(px0, px1);
        *(float2*)(sm + O_PARTY + jtg * 32 + e0) = make_float2(py0, py1);
        *(float2*)(sm + O_PARTZ + jtg * 32 + e0) = make_float2(pz0, pz1);
    }
    __syncthreads();
}

__global__ void __launch_bounds__(256) ode_kernel(
    const float* __restrict__ dynW1, const float* __restrict__ dynb1,
    const float* __restrict__ dynW2, const float* __restrict__ dynb2,
    const float* __restrict__ dynW3, const float* __restrict__ dynb3,
    const float* __restrict__ decW1, const float* __restrict__ decb1,
    const float* __restrict__ decW2, const float* __restrict__ decb2,
    const float* __restrict__ tsg,
    float* __restrict__ recon, float* __restrict__ traj)
{
    extern __shared__ float sm[];
    const int tid = threadIdx.x;

    // ---- stage weights into smem ----
    for (int i = tid; i < 112; i += 256) {
        if (i < 100) {
            ((float4*)(sm + O_W1B))[i] =
                make_float4(dynW1[i * 3], dynW1[i * 3 + 1], dynW1[i * 3 + 2], dynb1[i]);
            ((float4*)(sm + O_W3))[i] =
                make_float4(dynW3[i], dynW3[100 + i], dynW3[200 + i], 0.f);
            float b2v = dynb2[i];
            ((float2*)(sm + O_B2D))[i] = make_float2(b2v, b2v);
        } else {
            ((float4*)(sm + O_W1B))[i] = make_float4(0.f, 0.f, 0.f, 0.f);
            ((float4*)(sm + O_W3))[i]  = make_float4(0.f, 0.f, 0.f, 0.f);
            ((float2*)(sm + O_B2D))[i] = make_float2(0.f, 0.f);
        }
    }
    for (int i = tid; i < 64; i += 256) {
        ((float4*)(sm + O_DW1))[i] =
            make_float4(decW1[i * 3], decW1[i * 3 + 1], decW1[i * 3 + 2], decb1[i]);
        float bv = decb2[i];
        ((float2*)(sm + O_DB2D))[i] = make_float2(bv, bv);
    }
    for (int i = tid; i < 200; i += 256) sm[O_TS + i] = tsg[i];
    // W2 duplicated: [k][jtg*16 + jj*2 + {0,1}] = W2[jtg*7+jj][k]
    for (int idx = tid; idx < 104 * 256; idx += 256) {
        int k = idx >> 8;
        int s = idx & 255;
        int jtg = s >> 4;
        int jj = (s & 15) >> 1;
        int j = jtg * 7 + jj;
        float v = (jj < 7 && j < 100 && k < 100) ? dynW2[j * 100 + k] : 0.f;
        sm[O_W2D + idx] = v;
    }
    // decoder W2 duplicated: [k][og*8 + oo*2 + {0,1}] = decW2[og*4+oo][k]
    for (int idx = tid; idx < 64 * 128; idx += 256) {
        int k = idx >> 7;
        int s = idx & 127;
        int o = (s >> 3) * 4 + ((s & 7) >> 1);
        sm[O_DW2D + idx] = decW2[o * 64 + k];
    }
    __syncthreads();

    const int etg = tid & 15;       // dynf/fill mapping
    const int jtg = tid >> 4;
    const int e0 = etg * 2;
    const int og = tid & 15;        // decoder GEMM mapping
    const int eg = tid >> 4;
    const int ge0 = eg * 2;

    const float b3x = dynb3[0], b3y = dynb3[1], b3z = dynb3[2];

    float4 zc = make_float4(0.f, 0.f, 0.f, 0.f);
    if (tid < 32) {
        int b = blockIdx.x * 32 + tid;
        zc = make_float4(g_z0[b * 3], g_z0[b * 3 + 1], g_z0[b * 3 + 2], 0.f);
    }

    float4* zs0 = (float4*)(sm + O_ZS0);
    float4* zs1 = (float4*)(sm + O_ZS1);

    for (int t = 0; t < T_STEPS; ++t) {
        if (tid < 32) {
            zs0[tid] = zc;
            int b = blockIdx.x * 32 + tid;
            size_t to = ((size_t)t * BATCH + b) * 3;
            traj[to] = zc.x; traj[to + 1] = zc.y; traj[to + 2] = zc.z;
        }
        __syncthreads();

        // ---- decoder: HDT fill (etg/jtg mapping: jtg owns 4 h's) ----
        {
            float4 za = zs0[e0];
            float4 zb = zs0[e0 + 1];
            const float4* dw1 = (const float4*)(sm + O_DW1);
#pragma unroll
            for (int hh = 0; hh < 4; ++hh) {
                int h = jtg * 4 + hh;
                float4 w = dw1[h];
                float p0 = fmaf(za.x, w.x, fmaf(za.y, w.y, fmaf(za.z, w.z, w.w)));
                float p1 = fmaf(zb.x, w.x, fmaf(zb.y, w.y, fmaf(zb.z, w.z, w.w)));
                *(float2*)(sm + O_HDT + h * 32 + e0) =
                    make_float2(fmaxf(p0, 0.f), fmaxf(p1, 0.f));
            }
        }
        __syncthreads();
        // ---- decoder GEMM (og/eg mapping) + store ----
        {
            unsigned long long od[4];
#pragma unroll
            for (int oo = 0; oo < 4; ++oo)
                od[oo] = *(const unsigned long long*)(sm + O_DB2D + (og * 4 + oo) * 2);
            const float* abase = sm + O_HDT + ge0;
            const float* wbase = sm + O_DW2D + og * 8;
#pragma unroll 4
            for (int k = 0; k < 64; ++k) {
                unsigned long long a = *(const unsigned long long*)(abase + k * 32);
                const float* wr = wbase + k * 128;
                ulonglong2 wA = *(const ulonglong2*)(wr);
                ulonglong2 wB = *(const ulonglong2*)(wr + 4);
                fma2(od[0], a, wA.x);
                fma2(od[1], a, wA.y);
                fma2(od[2], a, wB.x);
                fma2(od[3], a, wB.y);
            }
            float2 r0 = unpack2(od[0]);
            float2 r1 = unpack2(od[1]);
            float2 r2 = unpack2(od[2]);
            float2 r3 = unpack2(od[3]);
            int b = blockIdx.x * 32 + ge0;
            float4* dA = (float4*)(recon + ((size_t)t * BATCH + b) * 64 + og * 4);
            float4* dB = (float4*)(recon + ((size_t)t * BATCH + b + 1) * 64 + og * 4);
            *dA = make_float4(r0.x, r1.x, r2.x, r3.x);
            *dB = make_float4(r0.y, r1.y, r2.y, r3.y);
        }

        if (t == T_STEPS - 1) break;

        float dt = sm[O_TS + t + 1] - sm[O_TS + t];
        float hh = 0.5f * dt;
        float4 zacc = zc;

        // ---- stage 1 ----
        dyn_stage(sm, zs0, etg, jtg, e0);
        if (tid < 32) {
            float kx = b3x, ky = b3y, kz = b3z;
#pragma unroll
            for (int i = 0; i < 16; ++i) {
                kx += sm[O_PARTX + i * 32 + tid];
                ky += sm[O_PARTY + i * 32 + tid];
                kz += sm[O_PARTZ + i * 32 + tid];
            }
            float c = dt * (1.0f / 6.0f);
            zacc.x = fmaf(c, kx, zacc.x);
            zacc.y = fmaf(c, ky, zacc.y);
            zacc.z = fmaf(c, kz, zacc.z);
            zs1[tid] = make_float4(fmaf(hh, kx, zc.x), fmaf(hh, ky, zc.y),
                                   fmaf(hh, kz, zc.z), 0.f);
        }
        __syncthreads();
        // ---- stage 2 ----
        dyn_stage(sm, zs1, etg, jtg, e0);
        if (tid < 32) {
            float kx = b3x, ky = b3y, kz = b3z;
#pragma unroll
            for (int i = 0; i < 16; ++i) {
                kx += sm[O_PARTX + i * 32 + tid];
                ky += sm[O_PARTY + i * 32 + tid];
                kz += sm[O_PARTZ + i * 32 + tid];
            }
            float c = dt * (1.0f / 3.0f);
            zacc.x = fmaf(c, kx, zacc.x);
            zacc.y = fmaf(c, ky, zacc.y);
            zacc.z = fmaf(c, kz, zacc.z);
            zs1[tid] = make_float4(fmaf(hh, kx, zc.x), fmaf(hh, ky, zc.y),
                                   fmaf(hh, kz, zc.z), 0.f);
        }
        __syncthreads();
        // ---- stage 3 ----
        dyn_stage(sm, zs1, etg, jtg, e0);
        if (tid < 32) {
            float kx = b3x, ky = b3y, kz = b3z;
#pragma unroll
            for (int i = 0; i < 16; ++i) {
                kx += sm[O_PARTX + i * 32 + tid];
                ky += sm[O_PARTY + i * 32 + tid];
                kz += sm[O_PARTZ + i * 32 + tid];
            }
            float c = dt * (1.0f / 3.0f);
            zacc.x = fmaf(c, kx, zacc.x);
            zacc.y = fmaf(c, ky, zacc.y);
            zacc.z = fmaf(c, kz, zacc.z);
            zs1[tid] = make_float4(fmaf(dt, kx, zc.x), fmaf(dt, ky, zc.y),
                                   fmaf(dt, kz, zc.z), 0.f);
        }
        __syncthreads();
        // ---- stage 4 ----
        dyn_stage(sm, zs1, etg, jtg, e0);
        if (tid < 32) {
            float kx = b3x, ky = b3y, kz = b3z;
#pragma unroll
            for (int i = 0; i < 16; ++i) {
                kx += sm[O_PARTX + i * 32 + tid];
                ky += sm[O_PARTY + i * 32 + tid];
                kz += sm[O_PARTZ + i * 32 + tid];
            }
            float c = dt * (1.0f / 6.0f);
            zc.x = fmaf(c, kx, zacc.x);
            zc.y = fmaf(c, ky, zacc.y);
            zc.z = fmaf(c, kz, zacc.z);
        }
        // zs0 write + sync at top of next iteration orders everything.
    }
}

// ===========================================================================
extern "C" void kernel_launch(void* const* d_in, const int* in_sizes, int n_in,
                              void* d_out, int out_size) {
    (void)in_sizes; (void)n_in; (void)out_size;
    const float* obs   = (const float*)d_in[0];
    const float* eps   = (const float*)d_in[1];
    const float* Wih   = (const float*)d_in[2];
    const float* Whh   = (const float*)d_in[3];
    const float* bih   = (const float*)d_in[4];
    const float* bhh   = (const float*)d_in[5];
    const float* meanW = (const float*)d_in[6];
    const float* meanb = (const float*)d_in[7];
    const float* logW  = (const float*)d_in[8];
    const float* logb  = (const float*)d_in[9];
    const float* dynW1 = (const float*)d_in[10];
    const float* dynb1 = (const float*)d_in[11];
    const float* dynW2 = (const float*)d_in[12];
    const float* dynb2 = (const float*)d_in[13];
    const float* dynW3 = (const float*)d_in[14];
    const float* dynb3 = (const float*)d_in[15];
    const float* decW1 = (const float*)d_in[16];
    const float* decb1 = (const float*)d_in[17];
    const float* decW2 = (const float*)d_in[18];
    const float* decb2 = (const float*)d_in[19];
    const float* ts    = (const float*)d_in[20];

    float* out   = (float*)d_out;
    float* recon = out;                      // [200,4096,64]
    float* omean = out + RECON_ELEMS;        // [4096,3]
    float* ologv = omean + ZM_ELEMS;         // [4096,3]
    float* traj  = ologv + ZM_ELEMS;         // [200,4096,3]

    cudaFuncSetAttribute(gru_kernel, cudaFuncAttributeMaxDynamicSharedMemorySize, GRU_SMEM_BYTES);
    cudaFuncSetAttribute(ode_kernel, cudaFuncAttributeMaxDynamicSharedMemorySize, ODE_SMEM_BYTES);

    dim3 g1(1600, 3);
    gi_gemm_kernel<<<g1, 256>>>(obs, Wih, bih);
    gru_kernel<<<128, 256, GRU_SMEM_BYTES>>>(Whh, bhh);
    z0_kernel<<<32, 128>>>(eps, meanW, meanb, logW, logb, omean, ologv);
    ode_kernel<<<128, 256, ODE_SMEM_BYTES>>>(dynW1, dynb1, dynW2, dynb2, dynW3, dynb3,
                                             decW1, decb1, decW2, decb2, ts, recon, traj);
}

// round 7
// speedup vs baseline: 3.7041x; 1.6985x over previous
#include <cuda_runtime.h>
#include <cuda_bf16.h>
#include <cstddef>
#include <cstdint>

#define T_STEPS 200
#define BATCH   4096
#define OBS     64
#define HID     128
#define NENC    50

#define RECON_ELEMS ((size_t)T_STEPS * BATCH * OBS)
#define ZM_ELEMS    ((size_t)BATCH * 3)

// Scratch (static device arrays; no runtime allocation)
__device__ float g_gi[(size_t)NENC * BATCH * 3 * HID];
__device__ float g_hlast[(size_t)BATCH * HID];
__device__ float g_z0[(size_t)BATCH * 3];

__device__ __forceinline__ float fsigmoid(float x) {
    return __fdividef(1.0f, 1.0f + __expf(-x));
}
__device__ __forceinline__ float ftanh(float x) {
    return 1.0f - __fdividef(2.0f, __expf(2.0f * x) + 1.0f);
}

// ---- packed fp32x2 helpers (Blackwell) ----
__device__ __forceinline__ void fma2(unsigned long long& d, unsigned long long a,
                                     unsigned long long b) {
    asm("fma.rn.f32x2 %0, %1, %2, %0;" : "+l"(d) : "l"(a), "l"(b));
}
__device__ __forceinline__ float2 unpack2(unsigned long long v) {
    float2 r;
    asm("mov.b64 {%0, %1}, %2;" : "=f"(r.x), "=f"(r.y) : "l"(v));
    return r;
}

// ===========================================================================
// Kernel 1: GI = obs[:50] @ Wih^T + bih  (NT SGEMM M=204800, N=384, K=64)
// ===========================================================================
__global__ void gi_gemm_kernel(const float* __restrict__ A,
                               const float* __restrict__ B,
                               const float* __restrict__ bias)
{
    __shared__ float As[16][128];
    __shared__ float Bs[16][128];
    const int tid = threadIdx.x;
    const int bm = blockIdx.x * 128;
    const int bn = blockIdx.y * 128;
    const int tx = tid & 15;
    const int ty = tid >> 4;

    float acc[8][8];
#pragma unroll
    for (int i = 0; i < 8; ++i)
#pragma unroll
        for (int j = 0; j < 8; ++j) acc[i][j] = 0.0f;

    for (int kk = 0; kk < 64; kk += 16) {
#pragma unroll
        for (int l = 0; l < 2; ++l) {
            int fi = tid + 256 * l;
            int row = fi >> 2;
            int kq = fi & 3;
            float4 va = *(const float4*)(A + (size_t)(bm + row) * 64 + kk + kq * 4);
            As[kq * 4 + 0][row] = va.x; As[kq * 4 + 1][row] = va.y;
            As[kq * 4 + 2][row] = va.z; As[kq * 4 + 3][row] = va.w;
            float4 vb = *(const float4*)(B + (size_t)(bn + row) * 64 + kk + kq * 4);
            Bs[kq * 4 + 0][row] = vb.x; Bs[kq * 4 + 1][row] = vb.y;
            Bs[kq * 4 + 2][row] = vb.z; Bs[kq * 4 + 3][row] = vb.w;
        }
        __syncthreads();
#pragma unroll
        for (int k = 0; k < 16; ++k) {
            float4 a0 = *(const float4*)&As[k][ty * 8];
            float4 a1 = *(const float4*)&As[k][ty * 8 + 4];
            float4 b0 = *(const float4*)&Bs[k][tx * 8];
            float4 b1 = *(const float4*)&Bs[k][tx * 8 + 4];
            float ar[8] = {a0.x, a0.y, a0.z, a0.w, a1.x, a1.y, a1.z, a1.w};
            float br[8] = {b0.x, b0.y, b0.z, b0.w, b1.x, b1.y, b1.z, b1.w};
#pragma unroll
            for (int i = 0; i < 8; ++i)
#pragma unroll
                for (int j = 0; j < 8; ++j)
                    acc[i][j] = fmaf(ar[i], br[j], acc[i][j]);
        }
        __syncthreads();
    }

    float bb[8];
#pragma unroll
    for (int j = 0; j < 8; ++j) bb[j] = bias[bn + tx * 8 + j];
#pragma unroll
    for (int i = 0; i < 8; ++i) {
        size_t rbase = (size_t)(bm + ty * 8 + i) * 384 + bn + tx * 8;
        float4 v0 = make_float4(acc[i][0] + bb[0], acc[i][1] + bb[1],
                                acc[i][2] + bb[2], acc[i][3] + bb[3]);
        float4 v1 = make_float4(acc[i][4] + bb[4], acc[i][5] + bb[5],
                                acc[i][6] + bb[6], acc[i][7] + bb[7]);
        *(float4*)(g_gi + rbase)     = v0;
        *(float4*)(g_gi + rbase + 4) = v1;
    }
}

// ===========================================================================
// Kernel 2: persistent GRU. Block owns 32 batch rows for all 50 steps.
// ===========================================================================
#define GRU_SMEM_BYTES ((3 * 128 * 128 + 32 * 128) * 4)

#define GRU_ACC4(A, W) \
    A[r][0] = fmaf(hv, W.x, A[r][0]); A[r][1] = fmaf(hv, W.y, A[r][1]); \
    A[r][2] = fmaf(hv, W.z, A[r][2]); A[r][3] = fmaf(hv, W.w, A[r][3]);

#define GRU_COMP(CC, GRc, GZc, GNc, HOc, HNc) {                           \
    float rr = fsigmoid(GRc + aR[r][CC] + bR[CC]);                        \
    float zz = fsigmoid(GZc + aZ[r][CC] + bZ[CC]);                        \
    float nn = ftanh(GNc + rr * (aN[r][CC] + bN[CC]));                    \
    HNc = fmaf(zz, HOc - nn, nn); }

__global__ void __launch_bounds__(256) gru_kernel(const float* __restrict__ Whh,
                                                  const float* __restrict__ bhh)
{
    extern __shared__ float sm[];
    float* WT = sm;                   // [g*128+k][u]
    float* hs = sm + 3 * 128 * 128;   // [32][128]
    const int tid = threadIdx.x;

    for (int idx = tid; idx < 3 * 128 * 128; idx += 256) {
        int row = idx >> 7;
        int k = idx & 127;
        int g = row >> 7, u = row & 127;
        WT[(g * 128 + k) * 128 + u] = Whh[idx];
    }
    for (int idx = tid; idx < 32 * 128; idx += 256) hs[idx] = 0.0f;
    __syncthreads();

    const int ug = tid & 31;
    const int rg = tid >> 5;
    const int row0 = blockIdx.x * 32;

    float bR[4], bZ[4], bN[4];
#pragma unroll
    for (int c = 0; c < 4; ++c) {
        bR[c] = bhh[ug * 4 + c];
        bZ[c] = bhh[128 + ug * 4 + c];
        bN[c] = bhh[256 + ug * 4 + c];
    }
    const float4* Wr4 = (const float4*)(WT);
    const float4* Wz4 = (const float4*)(WT + 128 * 128);
    const float4* Wn4 = (const float4*)(WT + 2 * 128 * 128);

    for (int t = 0; t < NENC; ++t) {
        float aR[4][4], aZ[4][4], aN[4][4];
#pragma unroll
        for (int r = 0; r < 4; ++r)
#pragma unroll
            for (int c = 0; c < 4; ++c) { aR[r][c] = 0.f; aZ[r][c] = 0.f; aN[r][c] = 0.f; }

#pragma unroll 2
        for (int k = 0; k < 128; ++k) {
            float4 wr = Wr4[k * 32 + ug];
            float4 wz = Wz4[k * 32 + ug];
            float4 wn = Wn4[k * 32 + ug];
#pragma unroll
            for (int r = 0; r < 4; ++r) {
                float hv = hs[(rg * 4 + r) * 128 + k];
                GRU_ACC4(aR, wr)
                GRU_ACC4(aZ, wz)
                GRU_ACC4(aN, wn)
            }
        }
        __syncthreads();

        const float* gbase = g_gi + ((size_t)t * BATCH + row0) * 384;
#pragma unroll
        for (int r = 0; r < 4; ++r) {
            int lr = rg * 4 + r;
            const float4* gf = (const float4*)(gbase + (size_t)lr * 384);
            float4 giR = gf[ug];
            float4 giZ = gf[32 + ug];
            float4 giN = gf[64 + ug];
            float4 hold = ((const float4*)(hs + lr * 128))[ug];
            float4 hn;
            GRU_COMP(0, giR.x, giZ.x, giN.x, hold.x, hn.x)
            GRU_COMP(1, giR.y, giZ.y, giN.y, hold.y, hn.y)
            GRU_COMP(2, giR.z, giZ.z, giN.z, hold.z, hn.z)
            GRU_COMP(3, giR.w, giZ.w, giN.w, hold.w, hn.w)
            ((float4*)(hs + lr * 128))[ug] = hn;
        }
        __syncthreads();
    }

    for (int idx = tid; idx < 32 * 128; idx += 256)
        g_hlast[(size_t)row0 * 128 + idx] = hs[idx];
}

// ===========================================================================
// Kernel 3: z0 head (one thread per batch row)
// ===========================================================================
__global__ void z0_kernel(const float* __restrict__ eps,
                          const float* __restrict__ meanW, const float* __restrict__ meanb,
                          const float* __restrict__ logW, const float* __restrict__ logb,
                          float* __restrict__ omean, float* __restrict__ ologv)
{
    const int b = blockIdx.x * 128 + threadIdx.x;
    const float4* h4 = (const float4*)(g_hlast + (size_t)b * 128);
    float m0 = 0.f, m1 = 0.f, m2 = 0.f, l0 = 0.f, l1 = 0.f, l2 = 0.f;
#pragma unroll
    for (int i = 0; i < 32; ++i) {
        float4 h = h4[i];
        float4 w;
        w = ((const float4*)meanW)[i];
        m0 = fmaf(h.x, w.x, fmaf(h.y, w.y, fmaf(h.z, w.z, fmaf(h.w, w.w, m0))));
        w = ((const float4*)(meanW + 128))[i];
        m1 = fmaf(h.x, w.x, fmaf(h.y, w.y, fmaf(h.z, w.z, fmaf(h.w, w.w, m1))));
        w = ((const float4*)(meanW + 256))[i];
        m2 = fmaf(h.x, w.x, fmaf(h.y, w.y, fmaf(h.z, w.z, fmaf(h.w, w.w, m2))));
        w = ((const float4*)logW)[i];
        l0 = fmaf(h.x, w.x, fmaf(h.y, w.y, fmaf(h.z, w.z, fmaf(h.w, w.w, l0))));
        w = ((const float4*)(logW + 128))[i];
        l1 = fmaf(h.x, w.x, fmaf(h.y, w.y, fmaf(h.z, w.z, fmaf(h.w, w.w, l1))));
        w = ((const float4*)(logW + 256))[i];
        l2 = fmaf(h.x, w.x, fmaf(h.y, w.y, fmaf(h.z, w.z, fmaf(h.w, w.w, l2))));
    }
    m0 += meanb[0]; m1 += meanb[1]; m2 += meanb[2];
    l0 += logb[0];  l1 += logb[1];  l2 += logb[2];
    omean[b * 3 + 0] = m0; omean[b * 3 + 1] = m1; omean[b * 3 + 2] = m2;
    ologv[b * 3 + 0] = l0; ologv[b * 3 + 1] = l1; ologv[b * 3 + 2] = l2;
    g_z0[b * 3 + 0] = fmaf(eps[b * 3 + 0], expf(0.5f * l0), m0);
    g_z0[b * 3 + 1] = fmaf(eps[b * 3 + 1], expf(0.5f * l1), m1);
    g_z0[b * 3 + 2] = fmaf(eps[b * 3 + 2], expf(0.5f * l2), m2);
}

// ===========================================================================
// Kernel 4: RK2(midpoint) ODE + fused decoder, j-packed f32x2 GEMMs.
// 256 thr/block, E=32 elems/block, grid=128.
// Layer2: etg=tid&15 (elem pair), jtg=tid>>4 (<13 active, 8 j's each).
// acc u64 packs {C[e][j0],C[e][j1]}; acts duplicated {h,h} in H1Td;
// weights UN-duplicated, contiguous W2[k][j].
// ===========================================================================
// smem float offsets (all 16B-aligned)
#define O_W1B   0        // 104 float4 (W1 row, b1); pads 0
#define O_W3    416      // 104 float4 (W3 col, 0); pads 0
#define O_B2P   832      // 104 floats b2 padded (u64 pairs)
#define O_DW1   936      // 64 float4 (decW1 row, decb1)
#define O_DB2P  1192     // 64 floats decb2
#define O_TS    1256     // 200 (+pad 8)
#define O_ZS0   1464     // 32 float4
#define O_ZS1   1592     // 32 float4
#define O_PARTX 1720     // [16][32] rows 13..15 stay 0
#define O_PARTY 2232
#define O_PARTZ 2744
#define O_H1TD  3256     // [104 k][64] = {h,h} per elem; rows 100..103 stay 0
#define O_HDTD  9912     // [64 k][64] = {h,h} per elem
#define O_W2    14008    // [104 k][104 j]  = W2[j][k], pads 0
#define O_DW2   24824    // [64 k][64 o]    = decW2[o][k]
#define ODE_SMEM_FLOATS 28920
#define ODE_SMEM_BYTES  (ODE_SMEM_FLOATS * 4)

typedef unsigned long long u64;

// one dynamics evaluation over the block's 32 elements.
// reads zin (float4[32]); leaves partX/Y/Z[jtg][e] ready. 2 internal syncs.
__device__ __forceinline__ void dyn_stage(float* sm, const float4* zin,
                                          int tid, int etg, int jtg)
{
    // ---- layer 1: flat tasks (j, elem-pair) -> H1Td[j][ep] = {t0,t0,t1,t1} ----
    const float4* w1 = (const float4*)(sm + O_W1B);
#pragma unroll
    for (int f = tid; f < 104 * 16; f += 256) {
        int j = f >> 4;
        int ep = f & 15;
        if (j < 100) {
            float4 w = w1[j];
            float4 za = zin[ep * 2];
            float4 zb = zin[ep * 2 + 1];
            float t0 = ftanh(fmaf(za.x, w.x, fmaf(za.y, w.y, fmaf(za.z, w.z, w.w))));
            float t1 = ftanh(fmaf(zb.x, w.x, fmaf(zb.y, w.y, fmaf(zb.z, w.z, w.w))));
            *(float4*)(sm + O_H1TD + j * 64 + ep * 4) = make_float4(t0, t0, t1, t1);
        }
    }
    __syncthreads();
    // ---- layer 2 (j-packed GEMM) + layer 3 ----
    if (jtg < 13) {
        u64 acc[2][4];
        {
            const u64* b2p = (const u64*)(sm + O_B2P + jtg * 8);
#pragma unroll
            for (int jp = 0; jp < 4; ++jp) { acc[0][jp] = b2p[jp]; acc[1][jp] = b2p[jp]; }
        }
        const float* abase = sm + O_H1TD + etg * 4;
        const float* wbase = sm + O_W2 + jtg * 8;
#pragma unroll 4
        for (int k = 0; k < 104; ++k) {
            ulonglong2 a = *(const ulonglong2*)(abase + k * 64);
            ulonglong2 w01 = *(const ulonglong2*)(wbase + k * 104);
            ulonglong2 w23 = *(const ulonglong2*)(wbase + k * 104 + 4);
            fma2(acc[0][0], a.x, w01.x);
            fma2(acc[0][1], a.x, w01.y);
            fma2(acc[0][2], a.x, w23.x);
            fma2(acc[0][3], a.x, w23.y);
            fma2(acc[1][0], a.y, w01.x);
            fma2(acc[1][1], a.y, w01.y);
            fma2(acc[1][2], a.y, w23.x);
            fma2(acc[1][3], a.y, w23.y);
        }
        // layer 3: tanh + W3 partials for this thread's 8 j's, 2 elems
        const float4* w3 = (const float4*)(sm + O_W3);
        float px[2] = {0.f, 0.f}, py[2] = {0.f, 0.f}, pz[2] = {0.f, 0.f};
#pragma unroll
        for (int e = 0; e < 2; ++e)
#pragma unroll
            for (int jp = 0; jp < 4; ++jp) {
                float2 c = unpack2(acc[e][jp]);
                float t0 = ftanh(c.x);
                float t1 = ftanh(c.y);
                float4 wa = w3[jtg * 8 + jp * 2];
                float4 wb = w3[jtg * 8 + jp * 2 + 1];
                px[e] = fmaf(t0, wa.x, fmaf(t1, wb.x, px[e]));
                py[e] = fmaf(t0, wa.y, fmaf(t1, wb.y, py[e]));
                pz[e] = fmaf(t0, wa.z, fmaf(t1, wb.z, pz[e]));
            }
        *(float2*)(sm + O_PARTX + jtg * 32 + etg * 2) = make_float2(px[0], px[1]);
        *(float2*)(sm + O_PARTY + jtg * 32 + etg * 2) = make_float2(py[0], py[1]);
        *(float2*)(sm + O_PARTZ + jtg * 32 + etg * 2) = make_float2(pz[0], pz[1]);
    }
    __syncthreads();
}

__global__ void __launch_bounds__(256) ode_kernel(
    const float* __restrict__ dynW1, const float* __restrict__ dynb1,
    const float* __restrict__ dynW2, const float* __restrict__ dynb2,
    const float* __restrict__ dynW3, const float* __restrict__ dynb3,
    const float* __restrict__ decW1, const float* __restrict__ decb1,
    const float* __restrict__ decW2, const float* __restrict__ decb2,
    const float* __restrict__ tsg,
    float* __restrict__ recon, float* __restrict__ traj)
{
    extern __shared__ float sm[];
    const int tid = threadIdx.x;

    // ---- stage weights into smem ----
    for (int i = tid; i < 104; i += 256) {
        if (i < 100) {
            ((float4*)(sm + O_W1B))[i] =
                make_float4(dynW1[i * 3], dynW1[i * 3 + 1], dynW1[i * 3 + 2], dynb1[i]);
            ((float4*)(sm + O_W3))[i] =
                make_float4(dynW3[i], dynW3[100 + i], dynW3[200 + i], 0.f);
            sm[O_B2P + i] = dynb2[i];
        } else {
            ((float4*)(sm + O_W1B))[i] = make_float4(0.f, 0.f, 0.f, 0.f);
            ((float4*)(sm + O_W3))[i]  = make_float4(0.f, 0.f, 0.f, 0.f);
            sm[O_B2P + i] = 0.f;
        }
    }
    for (int i = tid; i < 64; i += 256) {
        ((float4*)(sm + O_DW1))[i] =
            make_float4(decW1[i * 3], decW1[i * 3 + 1], decW1[i * 3 + 2], decb1[i]);
        sm[O_DB2P + i] = decb2[i];
    }
    for (int i = tid; i < 200; i += 256) sm[O_TS + i] = tsg[i];
    // W2: [k][j] = dynW2[j][k], pads 0
    for (int idx = tid; idx < 104 * 104; idx += 256) {
        int k = idx / 104, j = idx % 104;
        sm[O_W2 + idx] = (k < 100 && j < 100) ? dynW2[j * 100 + k] : 0.f;
    }
    // DW2: [k][o] = decW2[o][k]
    for (int idx = tid; idx < 64 * 64; idx += 256) {
        int k = idx >> 6, o = idx & 63;
        sm[O_DW2 + idx] = decW2[o * 64 + k];
    }
    // zero H1Td pad rows (k=100..103) and part rows 13..15 (once; never rewritten)
    for (int idx = tid; idx < 256; idx += 256)
        sm[O_H1TD + 100 * 64 + idx] = 0.f;
    for (int idx = tid; idx < 96; idx += 256) {
        sm[O_PARTX + 13 * 32 + idx] = 0.f;
        sm[O_PARTY + 13 * 32 + idx] = 0.f;
        sm[O_PARTZ + 13 * 32 + idx] = 0.f;
    }
    __syncthreads();

    const int etg = tid & 15;
    const int jtg = tid >> 4;

    const float b3x = dynb3[0], b3y = dynb3[1], b3z = dynb3[2];

    float4 zc = make_float4(0.f, 0.f, 0.f, 0.f);
    if (tid < 32) {
        int b = blockIdx.x * 32 + tid;
        zc = make_float4(g_z0[b * 3], g_z0[b * 3 + 1], g_z0[b * 3 + 2], 0.f);
    }

    float4* zs0 = (float4*)(sm + O_ZS0);
    float4* zs1 = (float4*)(sm + O_ZS1);

    for (int t = 0; t < T_STEPS; ++t) {
        if (tid < 32) {
            zs0[tid] = zc;
            int b = blockIdx.x * 32 + tid;
            size_t to = ((size_t)t * BATCH + b) * 3;
            traj[to] = zc.x; traj[to + 1] = zc.y; traj[to + 2] = zc.z;
        }
        __syncthreads();

        // ---- decoder: HDTd fill (flat tasks) ----
        {
            const float4* dw1 = (const float4*)(sm + O_DW1);
#pragma unroll
            for (int f = tid; f < 64 * 16; f += 256) {
                int h = f >> 4;
                int ep = f & 15;
                float4 w = dw1[h];
                float4 za = zs0[ep * 2];
                float4 zb = zs0[ep * 2 + 1];
                float p0 = fmaxf(fmaf(za.x, w.x, fmaf(za.y, w.y, fmaf(za.z, w.z, w.w))), 0.f);
                float p1 = fmaxf(fmaf(zb.x, w.x, fmaf(zb.y, w.y, fmaf(zb.z, w.z, w.w))), 0.f);
                *(float4*)(sm + O_HDTD + h * 64 + ep * 4) = make_float4(p0, p0, p1, p1);
            }
        }
        __syncthreads();
        // ---- decoder GEMM (o-packed) + store; all 16 og groups active ----
        {
            const int og = jtg;     // 16 groups x 4 outputs
            u64 od[2][2];
            {
                const u64* dbp = (const u64*)(sm + O_DB2P + og * 4);
                od[0][0] = dbp[0]; od[0][1] = dbp[1];
                od[1][0] = dbp[0]; od[1][1] = dbp[1];
            }
            const float* abase = sm + O_HDTD + etg * 4;
            const float* wbase = sm + O_DW2 + og * 4;
#pragma unroll 4
            for (int k = 0; k < 64; ++k) {
                ulonglong2 a = *(const ulonglong2*)(abase + k * 64);
                ulonglong2 w = *(const ulonglong2*)(wbase + k * 64);
                fma2(od[0][0], a.x, w.x);
                fma2(od[0][1], a.x, w.y);
                fma2(od[1][0], a.y, w.x);
                fma2(od[1][1], a.y, w.y);
            }
            float2 c00 = unpack2(od[0][0]);
            float2 c01 = unpack2(od[0][1]);
            float2 c10 = unpack2(od[1][0]);
            float2 c11 = unpack2(od[1][1]);
            int b = blockIdx.x * 32 + etg * 2;
            *(float4*)(recon + ((size_t)t * BATCH + b) * 64 + og * 4) =
                make_float4(c00.x, c00.y, c01.x, c01.y);
            *(float4*)(recon + ((size_t)t * BATCH + b + 1) * 64 + og * 4) =
                make_float4(c10.x, c10.y, c11.x, c11.y);
        }

        if (t == T_STEPS - 1) break;

        float dt = sm[O_TS + t + 1] - sm[O_TS + t];

        // ---- RK2 midpoint: k1 = f(z); z_mid = z + dt/2*k1; z += dt*f(z_mid) ----
        dyn_stage(sm, zs0, tid, etg, jtg);
        if (tid < 32) {
            float kx = b3x, ky = b3y, kz = b3z;
#pragma unroll
            for (int i = 0; i < 13; ++i) {
                kx += sm[O_PARTX + i * 32 + tid];
                ky += sm[O_PARTY + i * 32 + tid];
                kz += sm[O_PARTZ + i * 32 + tid];
            }
            float hh = 0.5f * dt;
            zs1[tid] = make_float4(fmaf(hh, kx, zc.x), fmaf(hh, ky, zc.y),
                                   fmaf(hh, kz, zc.z), 0.f);
        }
        __syncthreads();

        dyn_stage(sm, zs1, tid, etg, jtg);
        if (tid < 32) {
            float kx = b3x, ky = b3y, kz = b3z;
#pragma unroll
            for (int i = 0; i < 13; ++i) {
                kx += sm[O_PARTX + i * 32 + tid];
                ky += sm[O_PARTY + i * 32 + tid];
                kz += sm[O_PARTZ + i * 32 + tid];
            }
            zc.x = fmaf(dt, kx, zc.x);
            zc.y = fmaf(dt, ky, zc.y);
            zc.z = fmaf(dt, kz, zc.z);
        }
        // zs0 write + sync at top of next iteration orders everything.
    }
}

// ===========================================================================
extern "C" void kernel_launch(void* const* d_in, const int* in_sizes, int n_in,
                              void* d_out, int out_size) {
    (void)in_sizes; (void)n_in; (void)out_size;
    const float* obs   = (const float*)d_in[0];
    const float* eps   = (const float*)d_in[1];
    const float* Wih   = (const float*)d_in[2];
    const float* Whh   = (const float*)d_in[3];
    const float* bih   = (const float*)d_in[4];
    const float* bhh   = (const float*)d_in[5];
    const float* meanW = (const float*)d_in[6];
    const float* meanb = (const float*)d_in[7];
    const float* logW  = (const float*)d_in[8];
    const float* logb  = (const float*)d_in[9];
    const float* dynW1 = (const float*)d_in[10];
    const float* dynb1 = (const float*)d_in[11];
    const float* dynW2 = (const float*)d_in[12];
    const float* dynb2 = (const float*)d_in[13];
    const float* dynW3 = (const float*)d_in[14];
    const float* dynb3 = (const float*)d_in[15];
    const float* decW1 = (const float*)d_in[16];
    const float* decb1 = (const float*)d_in[17];
    const float* decW2 = (const float*)d_in[18];
    const float* decb2 = (const float*)d_in[19];
    const float* ts    = (const float*)d_in[20];

    float* out   = (float*)d_out;
    float* recon = out;                      // [200,4096,64]
    float* omean = out + RECON_ELEMS;        // [4096,3]
    float* ologv = omean + ZM_ELEMS;         // [4096,3]
    float* traj  = ologv + ZM_ELEMS;         // [200,4096,3]

    cudaFuncSetAttribute(gru_kernel, cudaFuncAttributeMaxDynamicSharedMemorySize, GRU_SMEM_BYTES);
    cudaFuncSetAttribute(ode_kernel, cudaFuncAttributeMaxDynamicSharedMemorySize, ODE_SMEM_BYTES);

    dim3 g1(1600, 3);
    gi_gemm_kernel<<<g1, 256>>>(obs, Wih, bih);
    gru_kernel<<<128, 256, GRU_SMEM_BYTES>>>(Whh, bhh);
    z0_kernel<<<32, 128>>>(eps, meanW, meanb, logW, logb, omean, ologv);
    ode_kernel<<<128, 256, ODE_SMEM_BYTES>>>(dynW1, dynb1, dynW2, dynb2, dynW3, dynb3,
                                             decW1, decb1, decW2, decb2, ts, recon, traj);
}

// round 8
// speedup vs baseline: 3.7045x; 1.0001x over previous
#include <cuda_runtime.h>
#include <cuda_bf16.h>
#include <cstddef>
#include <cstdint>

#define T_STEPS 200
#define BATCH   4096
#define OBS     64
#define HID     128
#define NENC    50

#define RECON_ELEMS ((size_t)T_STEPS * BATCH * OBS)
#define ZM_ELEMS    ((size_t)BATCH * 3)

// Scratch (static device arrays; no runtime allocation)
__device__ float g_gi[(size_t)NENC * BATCH * 3 * HID];
__device__ float g_hlast[(size_t)BATCH * HID];
__device__ float g_z0[(size_t)BATCH * 3];

__device__ __forceinline__ float fsigmoid(float x) {
    return __fdividef(1.0f, 1.0f + __expf(-x));
}
__device__ __forceinline__ float ftanh(float x) {
    return 1.0f - __fdividef(2.0f, __expf(2.0f * x) + 1.0f);
}

// ---- packed fp32x2 helpers (Blackwell) ----
__device__ __forceinline__ void fma2(unsigned long long& d, unsigned long long a,
                                     unsigned long long b) {
    asm("fma.rn.f32x2 %0, %1, %2, %0;" : "+l"(d) : "l"(a), "l"(b));
}
__device__ __forceinline__ float2 unpack2(unsigned long long v) {
    float2 r;
    asm("mov.b64 {%0, %1}, %2;" : "=f"(r.x), "=f"(r.y) : "l"(v));
    return r;
}

// ===========================================================================
// Kernel 1: GI = obs[:50] @ Wih^T + bih  (NT SGEMM M=204800, N=384, K=64)
// ===========================================================================
__global__ void gi_gemm_kernel(const float* __restrict__ A,
                               const float* __restrict__ B,
                               const float* __restrict__ bias)
{
    __shared__ float As[16][128];
    __shared__ float Bs[16][128];
    const int tid = threadIdx.x;
    const int bm = blockIdx.x * 128;
    const int bn = blockIdx.y * 128;
    const int tx = tid & 15;
    const int ty = tid >> 4;

    float acc[8][8];
#pragma unroll
    for (int i = 0; i < 8; ++i)
#pragma unroll
        for (int j = 0; j < 8; ++j) acc[i][j] = 0.0f;

    for (int kk = 0; kk < 64; kk += 16) {
#pragma unroll
        for (int l = 0; l < 2; ++l) {
            int fi = tid + 256 * l;
            int row = fi >> 2;
            int kq = fi & 3;
            float4 va = *(const float4*)(A + (size_t)(bm + row) * 64 + kk + kq * 4);
            As[kq * 4 + 0][row] = va.x; As[kq * 4 + 1][row] = va.y;
            As[kq * 4 + 2][row] = va.z; As[kq * 4 + 3][row] = va.w;
            float4 vb = *(const float4*)(B + (size_t)(bn + row) * 64 + kk + kq * 4);
            Bs[kq * 4 + 0][row] = vb.x; Bs[kq * 4 + 1][row] = vb.y;
            Bs[kq * 4 + 2][row] = vb.z; Bs[kq * 4 + 3][row] = vb.w;
        }
        __syncthreads();
#pragma unroll
        for (int k = 0; k < 16; ++k) {
            float4 a0 = *(const float4*)&As[k][ty * 8];
            float4 a1 = *(const float4*)&As[k][ty * 8 + 4];
            float4 b0 = *(const float4*)&Bs[k][tx * 8];
            float4 b1 = *(const float4*)&Bs[k][tx * 8 + 4];
            float ar[8] = {a0.x, a0.y, a0.z, a0.w, a1.x, a1.y, a1.z, a1.w};
            float br[8] = {b0.x, b0.y, b0.z, b0.w, b1.x, b1.y, b1.z, b1.w};
#pragma unroll
            for (int i = 0; i < 8; ++i)
#pragma unroll
                for (int j = 0; j < 8; ++j)
                    acc[i][j] = fmaf(ar[i], br[j], acc[i][j]);
        }
        __syncthreads();
    }

    float bb[8];
#pragma unroll
    for (int j = 0; j < 8; ++j) bb[j] = bias[bn + tx * 8 + j];
#pragma unroll
    for (int i = 0; i < 8; ++i) {
        size_t rbase = (size_t)(bm + ty * 8 + i) * 384 + bn + tx * 8;
        float4 v0 = make_float4(acc[i][0] + bb[0], acc[i][1] + bb[1],
                                acc[i][2] + bb[2], acc[i][3] + bb[3]);
        float4 v1 = make_float4(acc[i][4] + bb[4], acc[i][5] + bb[5],
                                acc[i][6] + bb[6], acc[i][7] + bb[7]);
        *(float4*)(g_gi + rbase)     = v0;
        *(float4*)(g_gi + rbase + 4) = v1;
    }
}

// ===========================================================================
// Kernel 2: persistent GRU. Block owns 32 batch rows for all 50 steps.
// ===========================================================================
#define GRU_SMEM_BYTES ((3 * 128 * 128 + 32 * 128) * 4)

#define GRU_ACC4(A, W) \
    A[r][0] = fmaf(hv, W.x, A[r][0]); A[r][1] = fmaf(hv, W.y, A[r][1]); \
    A[r][2] = fmaf(hv, W.z, A[r][2]); A[r][3] = fmaf(hv, W.w, A[r][3]);

#define GRU_COMP(CC, GRc, GZc, GNc, HOc, HNc) {                           \
    float rr = fsigmoid(GRc + aR[r][CC] + bR[CC]);                        \
    float zz = fsigmoid(GZc + aZ[r][CC] + bZ[CC]);                        \
    float nn = ftanh(GNc + rr * (aN[r][CC] + bN[CC]));                    \
    HNc = fmaf(zz, HOc - nn, nn); }

__global__ void __launch_bounds__(256) gru_kernel(const float* __restrict__ Whh,
                                                  const float* __restrict__ bhh)
{
    extern __shared__ float sm[];
    float* WT = sm;                   // [g*128+k][u]
    float* hs = sm + 3 * 128 * 128;   // [32][128]
    const int tid = threadIdx.x;

    for (int idx = tid; idx < 3 * 128 * 128; idx += 256) {
        int row = idx >> 7;
        int k = idx & 127;
        int g = row >> 7, u = row & 127;
        WT[(g * 128 + k) * 128 + u] = Whh[idx];
    }
    for (int idx = tid; idx < 32 * 128; idx += 256) hs[idx] = 0.0f;
    __syncthreads();

    const int ug = tid & 31;
    const int rg = tid >> 5;
    const int row0 = blockIdx.x * 32;

    float bR[4], bZ[4], bN[4];
#pragma unroll
    for (int c = 0; c < 4; ++c) {
        bR[c] = bhh[ug * 4 + c];
        bZ[c] = bhh[128 + ug * 4 + c];
        bN[c] = bhh[256 + ug * 4 + c];
    }
    const float4* Wr4 = (const float4*)(WT);
    const float4* Wz4 = (const float4*)(WT + 128 * 128);
    const float4* Wn4 = (const float4*)(WT + 2 * 128 * 128);

    for (int t = 0; t < NENC; ++t) {
        float aR[4][4], aZ[4][4], aN[4][4];
#pragma unroll
        for (int r = 0; r < 4; ++r)
#pragma unroll
            for (int c = 0; c < 4; ++c) { aR[r][c] = 0.f; aZ[r][c] = 0.f; aN[r][c] = 0.f; }

#pragma unroll 2
        for (int k = 0; k < 128; ++k) {
            float4 wr = Wr4[k * 32 + ug];
            float4 wz = Wz4[k * 32 + ug];
            float4 wn = Wn4[k * 32 + ug];
#pragma unroll
            for (int r = 0; r < 4; ++r) {
                float hv = hs[(rg * 4 + r) * 128 + k];
                GRU_ACC4(aR, wr)
                GRU_ACC4(aZ, wz)
                GRU_ACC4(aN, wn)
            }
        }
        __syncthreads();

        const float* gbase = g_gi + ((size_t)t * BATCH + row0) * 384;
#pragma unroll
        for (int r = 0; r < 4; ++r) {
            int lr = rg * 4 + r;
            const float4* gf = (const float4*)(gbase + (size_t)lr * 384);
            float4 giR = gf[ug];
            float4 giZ = gf[32 + ug];
            float4 giN = gf[64 + ug];
            float4 hold = ((const float4*)(hs + lr * 128))[ug];
            float4 hn;
            GRU_COMP(0, giR.x, giZ.x, giN.x, hold.x, hn.x)
            GRU_COMP(1, giR.y, giZ.y, giN.y, hold.y, hn.y)
            GRU_COMP(2, giR.z, giZ.z, giN.z, hold.z, hn.z)
            GRU_COMP(3, giR.w, giZ.w, giN.w, hold.w, hn.w)
            ((float4*)(hs + lr * 128))[ug] = hn;
        }
        __syncthreads();
    }

    for (int idx = tid; idx < 32 * 128; idx += 256)
        g_hlast[(size_t)row0 * 128 + idx] = hs[idx];
}

// ===========================================================================
// Kernel 3: z0 head (one thread per batch row)
// ===========================================================================
__global__ void z0_kernel(const float* __restrict__ eps,
                          const float* __restrict__ meanW, const float* __restrict__ meanb,
                          const float* __restrict__ logW, const float* __restrict__ logb,
                          float* __restrict__ omean, float* __restrict__ ologv)
{
    const int b = blockIdx.x * 128 + threadIdx.x;
    const float4* h4 = (const float4*)(g_hlast + (size_t)b * 128);
    float m0 = 0.f, m1 = 0.f, m2 = 0.f, l0 = 0.f, l1 = 0.f, l2 = 0.f;
#pragma unroll
    for (int i = 0; i < 32; ++i) {
        float4 h = h4[i];
        float4 w;
        w = ((const float4*)meanW)[i];
        m0 = fmaf(h.x, w.x, fmaf(h.y, w.y, fmaf(h.z, w.z, fmaf(h.w, w.w, m0))));
        w = ((const float4*)(meanW + 128))[i];
        m1 = fmaf(h.x, w.x, fmaf(h.y, w.y, fmaf(h.z, w.z, fmaf(h.w, w.w, m1))));
        w = ((const float4*)(meanW + 256))[i];
        m2 = fmaf(h.x, w.x, fmaf(h.y, w.y, fmaf(h.z, w.z, fmaf(h.w, w.w, m2))));
        w = ((const float4*)logW)[i];
        l0 = fmaf(h.x, w.x, fmaf(h.y, w.y, fmaf(h.z, w.z, fmaf(h.w, w.w, l0))));
        w = ((const float4*)(logW + 128))[i];
        l1 = fmaf(h.x, w.x, fmaf(h.y, w.y, fmaf(h.z, w.z, fmaf(h.w, w.w, l1))));
        w = ((const float4*)(logW + 256))[i];
        l2 = fmaf(h.x, w.x, fmaf(h.y, w.y, fmaf(h.z, w.z, fmaf(h.w, w.w, l2))));
    }
    m0 += meanb[0]; m1 += meanb[1]; m2 += meanb[2];
    l0 += logb[0];  l1 += logb[1];  l2 += logb[2];
    omean[b * 3 + 0] = m0; omean[b * 3 + 1] = m1; omean[b * 3 + 2] = m2;
    ologv[b * 3 + 0] = l0; ologv[b * 3 + 1] = l1; ologv[b * 3 + 2] = l2;
    g_z0[b * 3 + 0] = fmaf(eps[b * 3 + 0], expf(0.5f * l0), m0);
    g_z0[b * 3 + 1] = fmaf(eps[b * 3 + 1], expf(0.5f * l1), m1);
    g_z0[b * 3 + 2] = fmaf(eps[b * 3 + 2], expf(0.5f * l2), m2);
}

// ===========================================================================
// Kernel 4: RK2(midpoint) ODE + fused decoder, j-packed f32x2 GEMMs.
// 256 thr/block, E=32 elems/block, grid=128.
// Layer2: etg=tid&15 (elem pair), jtg=tid>>4 (<13 active, 8 j's each).
// acc u64 packs {C[e][j0],C[e][j1]}; acts duplicated {h,h} in H1Td;
// weights UN-duplicated, contiguous W2[k][j].
// ===========================================================================
// smem float offsets (all 16B-aligned)
#define O_W1B   0        // 104 float4 (W1 row, b1); pads 0
#define O_W3    416      // 104 float4 (W3 col, 0); pads 0
#define O_B2P   832      // 104 floats b2 padded (u64 pairs)
#define O_DW1   936      // 64 float4 (decW1 row, decb1)
#define O_DB2P  1192     // 64 floats decb2
#define O_TS    1256     // 200 (+pad 8)
#define O_ZS0   1464     // 32 float4
#define O_ZS1   1592     // 32 float4
#define O_PARTX 1720     // [16][32] rows 13..15 stay 0
#define O_PARTY 2232
#define O_PARTZ 2744
#define O_H1TD  3256     // [104 k][64] = {h,h} per elem; rows 100..103 stay 0
#define O_HDTD  9912     // [64 k][64] = {h,h} per elem
#define O_W2    14008    // [104 k][104 j]  = W2[j][k], pads 0
#define O_DW2   24824    // [64 k][64 o]    = decW2[o][k]
#define ODE_SMEM_FLOATS 28920
#define ODE_SMEM_BYTES  (ODE_SMEM_FLOATS * 4)

typedef unsigned long long u64;

// one dynamics evaluation over the block's 32 elements.
// reads zin (float4[32]); leaves partX/Y/Z[jtg][e] ready. 2 internal syncs.
__device__ __forceinline__ void dyn_stage(float* sm, const float4* zin,
                                          int tid, int etg, int jtg)
{
    // ---- layer 1: flat tasks (j, elem-pair) -> H1Td[j][ep] = {t0,t0,t1,t1} ----
    const float4* w1 = (const float4*)(sm + O_W1B);
#pragma unroll
    for (int f = tid; f < 104 * 16; f += 256) {
        int j = f >> 4;
        int ep = f & 15;
        if (j < 100) {
            float4 w = w1[j];
            float4 za = zin[ep * 2];
            float4 zb = zin[ep * 2 + 1];
            float t0 = ftanh(fmaf(za.x, w.x, fmaf(za.y, w.y, fmaf(za.z, w.z, w.w))));
            float t1 = ftanh(fmaf(zb.x, w.x, fmaf(zb.y, w.y, fmaf(zb.z, w.z, w.w))));
            *(float4*)(sm + O_H1TD + j * 64 + ep * 4) = make_float4(t0, t0, t1, t1);
        }
    }
    __syncthreads();
    // ---- layer 2 (j-packed GEMM) + layer 3 ----
    if (jtg < 13) {
        u64 acc[2][4];
        {
            const u64* b2p = (const u64*)(sm + O_B2P + jtg * 8);
#pragma unroll
            for (int jp = 0; jp < 4; ++jp) { acc[0][jp] = b2p[jp]; acc[1][jp] = b2p[jp]; }
        }
        const float* abase = sm + O_H1TD + etg * 4;
        const float* wbase = sm + O_W2 + jtg * 8;
#pragma unroll 4
        for (int k = 0; k < 104; ++k) {
            ulonglong2 a = *(const ulonglong2*)(abase + k * 64);
            ulonglong2 w01 = *(const ulonglong2*)(wbase + k * 104);
            ulonglong2 w23 = *(const ulonglong2*)(wbase + k * 104 + 4);
            fma2(acc[0][0], a.x, w01.x);
            fma2(acc[0][1], a.x, w01.y);
            fma2(acc[0][2], a.x, w23.x);
            fma2(acc[0][3], a.x, w23.y);
            fma2(acc[1][0], a.y, w01.x);
            fma2(acc[1][1], a.y, w01.y);
            fma2(acc[1][2], a.y, w23.x);
            fma2(acc[1][3], a.y, w23.y);
        }
        // layer 3: tanh + W3 partials for this thread's 8 j's, 2 elems
        const float4* w3 = (const float4*)(sm + O_W3);
        float px[2] = {0.f, 0.f}, py[2] = {0.f, 0.f}, pz[2] = {0.f, 0.f};
#pragma unroll
        for (int e = 0; e < 2; ++e)
#pragma unroll
            for (int jp = 0; jp < 4; ++jp) {
                float2 c = unpack2(acc[e][jp]);
                float t0 = ftanh(c.x);
                float t1 = ftanh(c.y);
                float4 wa = w3[jtg * 8 + jp * 2];
                float4 wb = w3[jtg * 8 + jp * 2 + 1];
                px[e] = fmaf(t0, wa.x, fmaf(t1, wb.x, px[e]));
                py[e] = fmaf(t0, wa.y, fmaf(t1, wb.y, py[e]));
                pz[e] = fmaf(t0, wa.z, fmaf(t1, wb.z, pz[e]));
            }
        *(float2*)(sm + O_PARTX + jtg * 32 + etg * 2) = make_float2(px[0], px[1]);
        *(float2*)(sm + O_PARTY + jtg * 32 + etg * 2) = make_float2(py[0], py[1]);
        *(float2*)(sm + O_PARTZ + jtg * 32 + etg * 2) = make_float2(pz[0], pz[1]);
    }
    __syncthreads();
}

__global__ void __launch_bounds__(256) ode_kernel(
    const float* __restrict__ dynW1, const float* __restrict__ dynb1,
    const float* __restrict__ dynW2, const float* __restrict__ dynb2,
    const float* __restrict__ dynW3, const float* __restrict__ dynb3,
    const float* __restrict__ decW1, const float* __restrict__ decb1,
    const float* __restrict__ decW2, const float* __restrict__ decb2,
    const float* __restrict__ tsg,
    float* __restrict__ recon, float* __restrict__ traj)
{
    extern __shared__ float sm[];
    const int tid = threadIdx.x;

    // ---- stage weights into smem ----
    for (int i = tid; i < 104; i += 256) {
        if (i < 100) {
            ((float4*)(sm + O_W1B))[i] =
                make_float4(dynW1[i * 3], dynW1[i * 3 + 1], dynW1[i * 3 + 2], dynb1[i]);
            ((float4*)(sm + O_W3))[i] =
                make_float4(dynW3[i], dynW3[100 + i], dynW3[200 + i], 0.f);
            sm[O_B2P + i] = dynb2[i];
        } else {
            ((float4*)(sm + O_W1B))[i] = make_float4(0.f, 0.f, 0.f, 0.f);
            ((float4*)(sm + O_W3))[i]  = make_float4(0.f, 0.f, 0.f, 0.f);
            sm[O_B2P + i] = 0.f;
        }
    }
    for (int i = tid; i < 64; i += 256) {
        ((float4*)(sm + O_DW1))[i] =
            make_float4(decW1[i * 3], decW1[i * 3 + 1], decW1[i * 3 + 2], decb1[i]);
        sm[O_DB2P + i] = decb2[i];
    }
    for (int i = tid; i < 200; i += 256) sm[O_TS + i] = tsg[i];
    // W2: [k][j] = dynW2[j][k], pads 0
    for (int idx = tid; idx < 104 * 104; idx += 256) {
        int k = idx / 104, j = idx % 104;
        sm[O_W2 + idx] = (k < 100 && j < 100) ? dynW2[j * 100 + k] : 0.f;
    }
    // DW2: [k][o] = decW2[o][k]
    for (int idx = tid; idx < 64 * 64; idx += 256) {
        int k = idx >> 6, o = idx & 63;
        sm[O_DW2 + idx] = decW2[o * 64 + k];
    }
    // zero H1Td pad rows (k=100..103) and part rows 13..15 (once; never rewritten)
    for (int idx = tid; idx < 256; idx += 256)
        sm[O_H1TD + 100 * 64 + idx] = 0.f;
    for (int idx = tid; idx < 96; idx += 256) {
        sm[O_PARTX + 13 * 32 + idx] = 0.f;
        sm[O_PARTY + 13 * 32 + idx] = 0.f;
        sm[O_PARTZ + 13 * 32 + idx] = 0.f;
    }
    __syncthreads();

    const int etg = tid & 15;
    const int jtg = tid >> 4;

    const float b3x = dynb3[0], b3y = dynb3[1], b3z = dynb3[2];

    float4 zc = make_float4(0.f, 0.f, 0.f, 0.f);
    if (tid < 32) {
        int b = blockIdx.x * 32 + tid;
        zc = make_float4(g_z0[b * 3], g_z0[b * 3 + 1], g_z0[b * 3 + 2], 0.f);
    }

    float4* zs0 = (float4*)(sm + O_ZS0);
    float4* zs1 = (float4*)(sm + O_ZS1);

    for (int t = 0; t < T_STEPS; ++t) {
        if (tid < 32) {
            zs0[tid] = zc;
            int b = blockIdx.x * 32 + tid;
            size_t to = ((size_t)t * BATCH + b) * 3;
            traj[to] = zc.x; traj[to + 1] = zc.y; traj[to + 2] = zc.z;
        }
        __syncthreads();

        // ---- decoder: HDTd fill (flat tasks) ----
        {
            const float4* dw1 = (const float4*)(sm + O_DW1);
#pragma unroll
            for (int f = tid; f < 64 * 16; f += 256) {
                int h = f >> 4;
                int ep = f & 15;
                float4 w = dw1[h];
                float4 za = zs0[ep * 2];
                float4 zb = zs0[ep * 2 + 1];
                float p0 = fmaxf(fmaf(za.x, w.x, fmaf(za.y, w.y, fmaf(za.z, w.z, w.w))), 0.f);
                float p1 = fmaxf(fmaf(zb.x, w.x, fmaf(zb.y, w.y, fmaf(zb.z, w.z, w.w))), 0.f);
                *(float4*)(sm + O_HDTD + h * 64 + ep * 4) = make_float4(p0, p0, p1, p1);
            }
        }
        __syncthreads();
        // ---- decoder GEMM (o-packed) + store; all 16 og groups active ----
        {
            const int og = jtg;     // 16 groups x 4 outputs
            u64 od[2][2];
            {
                const u64* dbp = (const u64*)(sm + O_DB2P + og * 4);
                od[0][0] = dbp[0]; od[0][1] = dbp[1];
                od[1][0] = dbp[0]; od[1][1] = dbp[1];
            }
            const float* abase = sm + O_HDTD + etg * 4;
            const float* wbase = sm + O_DW2 + og * 4;
#pragma unroll 4
            for (int k = 0; k < 64; ++k) {
                ulonglong2 a = *(const ulonglong2*)(abase + k * 64);
                ulonglong2 w = *(const ulonglong2*)(wbase + k * 64);
                fma2(od[0][0], a.x, w.x);
                fma2(od[0][1], a.x, w.y);
                fma2(od[1][0], a.y, w.x);
                fma2(od[1][1], a.y, w.y);
            }
            float2 c00 = unpack2(od[0][0]);
            float2 c01 = unpack2(od[0][1]);
            float2 c10 = unpack2(od[1][0]);
            float2 c11 = unpack2(od[1][1]);
            int b = blockIdx.x * 32 + etg * 2;
            *(float4*)(recon + ((size_t)t * BATCH + b) * 64 + og * 4) =
                make_float4(c00.x, c00.y, c01.x, c01.y);
            *(float4*)(recon + ((size_t)t * BATCH + b + 1) * 64 + og * 4) =
                make_float4(c10.x, c10.y, c11.x, c11.y);
        }

        if (t == T_STEPS - 1) break;

        float dt = sm[O_TS + t + 1] - sm[O_TS + t];

        // ---- RK2 midpoint: k1 = f(z); z_mid = z + dt/2*k1; z += dt*f(z_mid) ----
        dyn_stage(sm, zs0, tid, etg, jtg);
        if (tid < 32) {
            float kx = b3x, ky = b3y, kz = b3z;
#pragma unroll
            for (int i = 0; i < 13; ++i) {
                kx += sm[O_PARTX + i * 32 + tid];
                ky += sm[O_PARTY + i * 32 + tid];
                kz += sm[O_PARTZ + i * 32 + tid];
            }
            float hh = 0.5f * dt;
            zs1[tid] = make_float4(fmaf(hh, kx, zc.x), fmaf(hh, ky, zc.y),
                                   fmaf(hh, kz, zc.z), 0.f);
        }
        __syncthreads();

        dyn_stage(sm, zs1, tid, etg, jtg);
        if (tid < 32) {
            float kx = b3x, ky = b3y, kz = b3z;
#pragma unroll
            for (int i = 0; i < 13; ++i) {
                kx += sm[O_PARTX + i * 32 + tid];
                ky += sm[O_PARTY + i * 32 + tid];
                kz += sm[O_PARTZ + i * 32 + tid];
            }
            zc.x = fmaf(dt, kx, zc.x);
            zc.y = fmaf(dt, ky, zc.y);
            zc.z = fmaf(dt, kz, zc.z);
        }
        // zs0 write + sync at top of next iteration orders everything.
    }
}

// ===========================================================================
extern "C" void kernel_launch(void* const* d_in, const int* in_sizes, int n_in,
                              void* d_out, int out_size) {
    (void)in_sizes; (void)n_in; (void)out_size;
    const float* obs   = (const float*)d_in[0];
    const float* eps   = (const float*)d_in[1];
    const float* Wih   = (const float*)d_in[2];
    const float* Whh   = (const float*)d_in[3];
    const float* bih   = (const float*)d_in[4];
    const float* bhh   = (const float*)d_in[5];
    const float* meanW = (const float*)d_in[6];
    const float* meanb = (const float*)d_in[7];
    const float* logW  = (const float*)d_in[8];
    const float* logb  = (const float*)d_in[9];
    const float* dynW1 = (const float*)d_in[10];
    const float* dynb1 = (const float*)d_in[11];
    const float* dynW2 = (const float*)d_in[12];
    const float* dynb2 = (const float*)d_in[13];
    const float* dynW3 = (const float*)d_in[14];
    const float* dynb3 = (const float*)d_in[15];
    const float* decW1 = (const float*)d_in[16];
    const float* decb1 = (const float*)d_in[17];
    const float* decW2 = (const float*)d_in[18];
    const float* decb2 = (const float*)d_in[19];
    const float* ts    = (const float*)d_in[20];

    float* out   = (float*)d_out;
    float* recon = out;                      // [200,4096,64]
    float* omean = out + RECON_ELEMS;        // [4096,3]
    float* ologv = omean + ZM_ELEMS;         // [4096,3]
    float* traj  = ologv + ZM_ELEMS;         // [200,4096,3]

    cudaFuncSetAttribute(gru_kernel, cudaFuncAttributeMaxDynamicSharedMemorySize, GRU_SMEM_BYTES);
    cudaFuncSetAttribute(ode_kernel, cudaFuncAttributeMaxDynamicSharedMemorySize, ODE_SMEM_BYTES);

    dim3 g1(1600, 3);
    gi_gemm_kernel<<<g1, 256>>>(obs, Wih, bih);
    gru_kernel<<<128, 256, GRU_SMEM_BYTES>>>(Whh, bhh);
    z0_kernel<<<32, 128>>>(eps, meanW, meanb, logW, logb, omean, ologv);
    ode_kernel<<<128, 256, ODE_SMEM_BYTES>>>(dynW1, dynb1, dynW2, dynb2, dynW3, dynb3,
                                             decW1, decb1, decW2, decb2, ts, recon, traj);
}